// round 15
// baseline (speedup 1.0000x reference)
#include <cuda_runtime.h>
#include <cuda_bf16.h>
#include <math.h>
#include <stdint.h>

// ---------------- problem constants ----------------
#define PB   16
#define PS   512
#define PD   512
#define PH   8
#define PDK  64
#define PF   2048
#define PM   (PB*PS)          // 8192 rows
#define LN_EPS 1e-5f
typedef __nv_bfloat16 bf16;

// ---------------- scratch (device globals; no allocation) ----------------
__device__ float g_a [(size_t)PM * PD];
__device__ float g_a1[(size_t)PM * PD];
__device__ float g_t [(size_t)PM * PD];
__device__ float g_x [(size_t)PM * PD];

// bf16 hi/lo pair planes
__device__ bf16 p_e1h[(size_t)PM*PD], p_e1l[(size_t)PM*PD];
__device__ bf16 p_e2h[(size_t)PM*PD], p_e2l[(size_t)PM*PD];
__device__ bf16 p_qh[(size_t)PM*PD],  p_ql[(size_t)PM*PD];
__device__ bf16 p_vh[(size_t)PM*PD],  p_vl[(size_t)PM*PD];
__device__ bf16 p_q1h[(size_t)PM*PD], p_q1l[(size_t)PM*PD];
__device__ bf16 p_v1h[(size_t)PM*PD], p_v1l[(size_t)PM*PD];
__device__ bf16 p_oh[(size_t)PM*PD],  p_ol[(size_t)PM*PD];
__device__ bf16 p_o1h[(size_t)PM*PD], p_o1l[(size_t)PM*PD];
__device__ bf16 p_th[(size_t)PM*PD],  p_tl[(size_t)PM*PD];
__device__ bf16 p_yh[(size_t)PM*PD],  p_yl[(size_t)PM*PD];
__device__ bf16 p_xh[(size_t)PM*PD],  p_xl[(size_t)PM*PD];
__device__ bf16 p_hh[(size_t)PM*PF],  p_hl[(size_t)PM*PF];
__device__ bf16 p_wkh[(size_t)3*PD*PD], p_wkl[(size_t)3*PD*PD];
__device__ bf16 p_wvh[(size_t)3*PD*PD], p_wvl[(size_t)3*PD*PD];
__device__ bf16 p_woh[(size_t)3*PD*PD], p_wol[(size_t)3*PD*PD];
__device__ bf16 p_w1h[(size_t)3*PD*PF], p_w1l[(size_t)3*PD*PF];
__device__ bf16 p_w2h[(size_t)3*PF*PD], p_w2l[(size_t)3*PF*PD];

// ---------------- helpers ----------------
__device__ __forceinline__ uint32_t smem_u32(const void* p) {
    uint32_t a;
    asm("{ .reg .u64 t; cvta.to.shared.u64 t, %1; cvt.u32.u64 %0, t; }"
        : "=r"(a) : "l"(p));
    return a;
}
__device__ __forceinline__ float warpMax(float v) {
#pragma unroll
    for (int o = 16; o; o >>= 1) v = fmaxf(v, __shfl_xor_sync(0xffffffffu, v, o));
    return v;
}
__device__ __forceinline__ float warpSum(float v) {
#pragma unroll
    for (int o = 16; o; o >>= 1) v += __shfl_xor_sync(0xffffffffu, v, o);
    return v;
}
__device__ __forceinline__ uint32_t split_pack(float x, float y, uint32_t& lo_pack) {
    bf16 hx = __float2bfloat16_rn(x);
    bf16 hy = __float2bfloat16_rn(y);
    bf16 lx = __float2bfloat16_rn(x - __bfloat162float(hx));
    bf16 ly = __float2bfloat16_rn(y - __bfloat162float(hy));
    lo_pack = ((uint32_t)__bfloat16_as_ushort(ly) << 16) | (uint32_t)__bfloat16_as_ushort(lx);
    return ((uint32_t)__bfloat16_as_ushort(hy) << 16) | (uint32_t)__bfloat16_as_ushort(hx);
}
__device__ __forceinline__ void ldsm_x4(uint32_t* r, uint32_t addr) {
    asm volatile("ldmatrix.sync.aligned.m8n8.x4.shared.b16 {%0,%1,%2,%3}, [%4];"
                 : "=r"(r[0]), "=r"(r[1]), "=r"(r[2]), "=r"(r[3]) : "r"(addr));
}
__device__ __forceinline__ void ldsm_x2(uint32_t* r, uint32_t addr) {
    asm volatile("ldmatrix.sync.aligned.m8n8.x2.shared.b16 {%0,%1}, [%2];"
                 : "=r"(r[0]), "=r"(r[1]) : "r"(addr));
}
__device__ __forceinline__ void ldsm_x2t(uint32_t* r, uint32_t addr) {
    asm volatile("ldmatrix.sync.aligned.m8n8.x2.trans.shared.b16 {%0,%1}, [%2];"
                 : "=r"(r[0]), "=r"(r[1]) : "r"(addr));
}
__device__ __forceinline__ void mma_bf16(float c[4], const uint32_t a[4], const uint32_t b[2]) {
    asm volatile(
        "mma.sync.aligned.m16n8k16.row.col.f32.bf16.bf16.f32 "
        "{%0,%1,%2,%3}, {%4,%5,%6,%7}, {%8,%9}, {%0,%1,%2,%3};"
        : "+f"(c[0]), "+f"(c[1]), "+f"(c[2]), "+f"(c[3])
        : "r"(a[0]), "r"(a[1]), "r"(a[2]), "r"(a[3]), "r"(b[0]), "r"(b[1]));
}
__device__ __forceinline__ void cp16(uint32_t dst, const void* src) {
    asm volatile("cp.async.cg.shared.global [%0], [%1], 16;"
                 :: "r"(dst), "l"(src) : "memory");
}
#define CP_COMMIT() asm volatile("cp.async.commit_group;" ::: "memory")
#define CP_WAIT0()  asm volatile("cp.async.wait_group 0;" ::: "memory")

// ---------------- fp32 -> bf16 hi/lo conversion (all tensors, one launch) ----------------
struct ConvDesc { const float* s; bf16* h; bf16* l; int n4; };
struct ConvArgs { ConvDesc d[7]; };

__global__ __launch_bounds__(256) void conv_all(ConvArgs a)
{
    ConvDesc d = a.d[blockIdx.y];
    int i = blockIdx.x * 256 + threadIdx.x;
    if (i < d.n4) {
        float4 v = ((const float4*)d.s)[i];
        uint32_t lo0, lo1;
        uint32_t h0 = split_pack(v.x, v.y, lo0);
        uint32_t h1 = split_pack(v.z, v.w, lo1);
        ((uint2*)d.h)[i] = make_uint2(h0, h1);
        ((uint2*)d.l)[i] = make_uint2(lo0, lo1);
    }
}

// ======================= bf16x3 tensor-core GEMM (cp.async) =======================
// CTA tile 128x128, K-chunk 32, 2-stage cp.async, 256 threads, 2 CTAs/SM.
// Single __syncthreads per chunk: wait -> sync -> issue(ck+1) -> compute(ck).
#define SA_HI 0
#define SA_LO 10240
#define SB_HI 20480
#define SB_LO 29184
#define STAGE 37888
#define GEMM_SMEM (2 * STAGE)

template <int OUTMODE>
__device__ __forceinline__ void gemm_core(
    const bf16* __restrict__ Ah, const bf16* __restrict__ Al,
    const bf16* __restrict__ Wh, const bf16* __restrict__ Wl,
    const float* __restrict__ bias,
    float* __restrict__ C, bf16* __restrict__ Ch, bf16* __restrict__ Cl,
    int Mv, int Nv, int Kv, char* smem_raw)
{
    const uint32_t smb = smem_u32(smem_raw);
    const int tid = threadIdx.x;
    const int lane = tid & 31;
    const int wid = tid >> 5;
    const int wm = (wid >> 2) * 64;
    const int wn = (wid & 3) * 32;
    const int by = blockIdx.y * 128;
    const int bx = blockIdx.x * 128;
    const int nC = Kv >> 5;

    float c[4][4][4] = {};
    const int aRow = (lane & 7) + ((lane >> 3) & 1) * 8;
    const int aCol = (lane >> 4) * 8;
    const int bRow = lane & 15;

    auto issue = [&](int ck) {
        const uint32_t sb = smb + (ck & 1) * STAGE;
        const int k0 = ck * 32;
#pragma unroll
        for (int i = 0; i < 2; i++) {
            int idx = tid + i * 256;
            int r = idx >> 2, s = idx & 3;
            size_t go = (size_t)(by + r) * Kv + k0 + s * 8;
            cp16(sb + SA_HI + r * 80 + s * 16, Ah + go);
            cp16(sb + SA_LO + r * 80 + s * 16, Al + go);
        }
#pragma unroll
        for (int i = 0; i < 2; i++) {
            int idx = tid + i * 256;
            int r = idx >> 4, s = idx & 15;
            size_t go = (size_t)(k0 + r) * Nv + bx + s * 8;
            cp16(sb + SB_HI + r * 272 + s * 16, Wh + go);
            cp16(sb + SB_LO + r * 272 + s * 16, Wl + go);
        }
        CP_COMMIT();
    };

    issue(0);

    for (int ck = 0; ck < nC; ck++) {
        CP_WAIT0();          // only group ck is outstanding here
        __syncthreads();     // data visible + all warps done with compute(ck-1)
        if (ck + 1 < nC) issue(ck + 1);   // overwrites buffer consumed at ck-1: safe

        const uint32_t sb = smb + (ck & 1) * STAGE;
#pragma unroll
        for (int ks = 0; ks < 32; ks += 16) {
            uint32_t ah[4][4], al[4][4], bh[4][2], bl[4][2];
#pragma unroll
            for (int mt = 0; mt < 4; mt++) {
                uint32_t off = (uint32_t)((wm + mt * 16 + aRow) * 80 + (ks + aCol) * 2);
                ldsm_x4(ah[mt], sb + SA_HI + off);
                ldsm_x4(al[mt], sb + SA_LO + off);
            }
#pragma unroll
            for (int nt = 0; nt < 4; nt++) {
                uint32_t off = (uint32_t)((ks + bRow) * 272 + (wn + nt * 8) * 2);
                ldsm_x2t(bh[nt], sb + SB_HI + off);
                ldsm_x2t(bl[nt], sb + SB_LO + off);
            }
#pragma unroll
            for (int mt = 0; mt < 4; mt++)
#pragma unroll
                for (int nt = 0; nt < 4; nt++) {
                    mma_bf16(c[mt][nt], ah[mt], bh[nt]);
                    mma_bf16(c[mt][nt], ah[mt], bl[nt]);
                    mma_bf16(c[mt][nt], al[mt], bh[nt]);
                }
        }
    }

    const int g = lane >> 2, t = lane & 3;
#pragma unroll
    for (int mt = 0; mt < 4; mt++) {
#pragma unroll
        for (int nt = 0; nt < 4; nt++) {
            int row = by + wm + mt * 16 + g;
            int col = bx + wn + nt * 8 + 2 * t;
            float2 bv = *(const float2*)(bias + col);
            float v00 = c[mt][nt][0] + bv.x, v01 = c[mt][nt][1] + bv.y;
            float v10 = c[mt][nt][2] + bv.x, v11 = c[mt][nt][3] + bv.y;
            if (OUTMODE == 2) {
                v00 = fmaxf(v00, 0.f); v01 = fmaxf(v01, 0.f);
                v10 = fmaxf(v10, 0.f); v11 = fmaxf(v11, 0.f);
            }
            if (OUTMODE == 0) {
                *(float2*)(C + (size_t)row * Nv + col) = make_float2(v00, v01);
                *(float2*)(C + (size_t)(row + 8) * Nv + col) = make_float2(v10, v11);
            } else {
                uint32_t lo0, lo1;
                uint32_t h0 = split_pack(v00, v01, lo0);
                uint32_t h1 = split_pack(v10, v11, lo1);
                *(uint32_t*)(Ch + (size_t)row * Nv + col) = h0;
                *(uint32_t*)(Cl + (size_t)row * Nv + col) = lo0;
                *(uint32_t*)(Ch + (size_t)(row + 8) * Nv + col) = h1;
                *(uint32_t*)(Cl + (size_t)(row + 8) * Nv + col) = lo1;
            }
        }
    }
}

template <int OUTMODE>
__global__ __launch_bounds__(256, 2)
void gemm_mma(const bf16* __restrict__ Ah, const bf16* __restrict__ Al,
              const bf16* __restrict__ Wh, const bf16* __restrict__ Wl,
              const float* __restrict__ bias,
              float* __restrict__ C, bf16* __restrict__ Ch, bf16* __restrict__ Cl,
              int Mv, int Nv, int Kv)
{
    extern __shared__ __align__(128) char smem_raw[];
    gemm_core<OUTMODE>(Ah, Al, Wh, Wl, bias, C, Ch, Cl, Mv, Nv, Kv, smem_raw);
}

// multi-set GEMM: blockIdx.z selects pointer set
struct GSet  { const bf16 *Ah, *Al, *Wh, *Wl; const float* bias; float* C; bf16 *Ch, *Cl; };
struct GSets { GSet s[4]; };

template <int OUTMODE>
__global__ __launch_bounds__(256, 2)
void gemm_multi(GSets sets, int Mv, int Nv, int Kv)
{
    extern __shared__ __align__(128) char smem_raw[];
    GSet g = sets.s[blockIdx.z];
    gemm_core<OUTMODE>(g.Ah, g.Al, g.Wh, g.Wl, g.bias, g.C, g.Ch, g.Cl,
                       Mv, Nv, Kv, smem_raw);
}

// ---------------- fused add + LayerNorm (warp-per-row) ----------------
template <int MODE>
__device__ __forceinline__ void add_ln_row(
    int row,
    const float* __restrict__ A, const float* __restrict__ Bv,
    const float* __restrict__ g, const float* __restrict__ be,
    float* __restrict__ outF, bf16* __restrict__ outH, bf16* __restrict__ outL)
{
    const int lane = threadIdx.x & 31;
    float4 x4[4];
    float sum = 0.f;
#pragma unroll
    for (int i = 0; i < 4; i++) {
        int idx = lane + i * 32;
        float4 xa = ((const float4*)(A  + (size_t)row * PD))[idx];
        float4 xb = ((const float4*)(Bv + (size_t)row * PD))[idx];
        x4[i].x = xa.x + xb.x; x4[i].y = xa.y + xb.y;
        x4[i].z = xa.z + xb.z; x4[i].w = xa.w + xb.w;
        sum += x4[i].x + x4[i].y + x4[i].z + x4[i].w;
    }
    float mean = warpSum(sum) * (1.0f / PD);
    float vs = 0.f;
#pragma unroll
    for (int i = 0; i < 4; i++) {
        x4[i].x -= mean; x4[i].y -= mean; x4[i].z -= mean; x4[i].w -= mean;
        vs += x4[i].x * x4[i].x + x4[i].y * x4[i].y +
              x4[i].z * x4[i].z + x4[i].w * x4[i].w;
    }
    float rstd = rsqrtf(warpSum(vs) * (1.0f / PD) + LN_EPS);
#pragma unroll
    for (int i = 0; i < 4; i++) {
        int idx = lane + i * 32;
        float4 gg = ((const float4*)g)[idx];
        float4 bb = ((const float4*)be)[idx];
        float o0 = x4[i].x * rstd * gg.x + bb.x;
        float o1 = x4[i].y * rstd * gg.y + bb.y;
        float o2 = x4[i].z * rstd * gg.z + bb.z;
        float o3 = x4[i].w * rstd * gg.w + bb.w;
        if (MODE != 1)
            ((float4*)(outF + (size_t)row * PD))[idx] = make_float4(o0, o1, o2, o3);
        if (MODE != 0) {
            uint32_t lo0, lo1;
            uint32_t h0 = split_pack(o0, o1, lo0);
            uint32_t h1 = split_pack(o2, o3, lo1);
            ((uint2*)(outH + (size_t)row * PD))[idx] = make_uint2(h0, h1);
            ((uint2*)(outL + (size_t)row * PD))[idx] = make_uint2(lo0, lo1);
        }
    }
}

template <int MODE>
__global__ __launch_bounds__(256) void add_ln_kernel(
    const float* __restrict__ A, const float* __restrict__ Bv,
    const float* __restrict__ g, const float* __restrict__ be,
    float* __restrict__ outF, bf16* __restrict__ outH, bf16* __restrict__ outL)
{
    int row = blockIdx.x * 8 + (threadIdx.x >> 5);
    add_ln_row<MODE>(row, A, Bv, g, be, outF, outH, outL);
}

__global__ __launch_bounds__(256) void add_ln_dual(
    const float* A0, const float* B0, const float* g0, const float* be0,
    float* f0, bf16* h0, bf16* l0,
    const float* A1, const float* B1, const float* g1, const float* be1,
    float* f1, bf16* h1, bf16* l1)
{
    int row = blockIdx.x * 8 + (threadIdx.x >> 5);
    if (blockIdx.y == 0)
        add_ln_row<2>(row, A0, B0, g0, be0, f0, h0, l0);
    else
        add_ln_row<2>(row, A1, B1, g1, be1, f1, h1, l1);
}

// ---------------- fused distance-decay attention (tensor-core) ----------------
#define AQ_H 0
#define AQ_L 4608
#define AK_H 9216
#define AK_L 27648
#define A_SS 46080
#define ATT_SMEM 112640

__device__ __forceinline__ void attn_core(
    const bf16* __restrict__ Qh, const bf16* __restrict__ Ql,
    const bf16* __restrict__ Vh, const bf16* __restrict__ Vl,
    const float* __restrict__ gammas, int layer, int strict,
    bf16* __restrict__ Oh, bf16* __restrict__ Ol, char* sm_raw)
{
    const uint32_t smb = smem_u32(sm_raw);
    float* sS = (float*)(sm_raw + A_SS);

    const int bh = blockIdx.y;
    const int b = bh >> 3, h = bh & 7;
    const int i0 = blockIdx.x * 32;
    const int tid = threadIdx.x;
    const int lane = tid & 31, w = tid >> 5;

    int nCh = (i0 + 32 + 127) >> 7;
    if (strict && i0 == 0) nCh = 4;
    const int jEnd = nCh * 128;

    float gamma = gammas[layer * PH + h];
    float gneg = (gamma > 20.f) ? -gamma : -log1pf(expf(gamma));

    const size_t headOff = (size_t)(b * PS) * PD + h * PDK;
    const bf16* Qbh = Qh + headOff;
    const bf16* Qbl = Ql + headOff;
    const bf16* Vbh = Vh + headOff;
    const bf16* Vbl = Vl + headOff;

    const int aRow = (lane & 7) + ((lane >> 3) & 1) * 8;
    const int aCol = (lane >> 4) * 8;
    const int g = lane >> 2, t = lane & 3;

    {
        int r = tid >> 3, s = tid & 7;
        *(uint4*)(sm_raw + AQ_H + r * 144 + s * 16) =
            *(const uint4*)(Qbh + (size_t)(i0 + r) * PD + s * 8);
        *(uint4*)(sm_raw + AQ_L + r * 144 + s * 16) =
            *(const uint4*)(Qbl + (size_t)(i0 + r) * PD + s * 8);
    }

    for (int j0 = 0; j0 < jEnd; j0 += 128) {
#pragma unroll
        for (int i = 0; i < 4; i++) {
            int idx = tid + i * 256;
            int r = idx >> 3, s = idx & 7;
            *(uint4*)(sm_raw + AK_H + r * 144 + s * 16) =
                *(const uint4*)(Qbh + (size_t)(j0 + r) * PD + s * 8);
            *(uint4*)(sm_raw + AK_L + r * 144 + s * 16) =
                *(const uint4*)(Qbl + (size_t)(j0 + r) * PD + s * 8);
        }
        __syncthreads();

        float acc[2][2][4] = {};
#pragma unroll
        for (int ks = 0; ks < 64; ks += 16) {
            uint32_t ah[2][4], al[2][4], kh[2][2], kl[2][2];
#pragma unroll
            for (int mt = 0; mt < 2; mt++) {
                uint32_t off = (uint32_t)((mt * 16 + aRow) * 144 + (ks + aCol) * 2);
                ldsm_x4(ah[mt], smb + AQ_H + off);
                ldsm_x4(al[mt], smb + AQ_L + off);
            }
#pragma unroll
            for (int nf = 0; nf < 2; nf++) {
                uint32_t off = (uint32_t)((w * 16 + nf * 8 + (lane & 7)) * 144 +
                                          (ks + ((lane >> 3) & 1) * 8) * 2);
                ldsm_x2(kh[nf], smb + AK_H + off);
                ldsm_x2(kl[nf], smb + AK_L + off);
            }
#pragma unroll
            for (int mt = 0; mt < 2; mt++)
#pragma unroll
                for (int nf = 0; nf < 2; nf++) {
                    mma_bf16(acc[mt][nf], ah[mt], kh[nf]);
                    mma_bf16(acc[mt][nf], ah[mt], kl[nf]);
                    mma_bf16(acc[mt][nf], al[mt], kh[nf]);
                }
        }
        const float scale = 0.125f;
#pragma unroll
        for (int mt = 0; mt < 2; mt++)
#pragma unroll
            for (int nf = 0; nf < 2; nf++) {
                int r0 = mt * 16 + g;
                int col = j0 + w * 16 + nf * 8 + 2 * t;
                *(float2*)&sS[r0 * 520 + col] =
                    make_float2(acc[mt][nf][0] * scale, acc[mt][nf][1] * scale);
                *(float2*)&sS[(r0 + 8) * 520 + col] =
                    make_float2(acc[mt][nf][2] * scale, acc[mt][nf][3] * scale);
            }
        __syncthreads();
    }

    const float NEG = -1e32f;
    for (int rr = 0; rr < 4; rr++) {
        const int il = w + rr * 8;
        const int ig = i0 + il;
        const uint32_t pSw = (uint32_t)(((il >> 2) & 1) * 16);
        float sraw[16], p[16], cum[16];
        float mx = NEG;
#pragma unroll
        for (int c = 0; c < 16; c++) {
            int j = lane + 32 * c;
            sraw[c] = sS[il * 520 + j];
            bool vld = strict ? (j < ig) : (j <= ig);
            float s1 = vld ? sraw[c] : NEG;
            p[c] = s1;
            mx = fmaxf(mx, s1);
        }
        mx = warpMax(mx);
        float sum = 0.f;
#pragma unroll
        for (int c = 0; c < 16; c++) { float e = __expf(p[c] - mx); p[c] = e; sum += e; }
        sum = warpSum(sum);
        float inv = 1.0f / sum;
#pragma unroll
        for (int c = 0; c < 16; c++) {
            int j = lane + 32 * c;
            bool vld = strict ? (j < ig) : (j <= ig);
            p[c] = vld ? p[c] * inv : 0.f;
        }
        float run = 0.f;
#pragma unroll
        for (int c = 0; c < 16; c++) {
            float sc = p[c];
#pragma unroll
            for (int o = 1; o < 32; o <<= 1) {
                float tt = __shfl_up_sync(0xffffffffu, sc, o);
                if (lane >= o) sc += tt;
            }
            cum[c] = run + sc;
            run += __shfl_sync(0xffffffffu, sc, 31);
        }
        const float tot = run;
        float m2 = NEG;
#pragma unroll
        for (int c = 0; c < 16; c++) {
            int j = lane + 32 * c;
            bool vld = strict ? (j < ig) : (j <= ig);
            float pos = fabsf((float)(ig - j));
            float dist = sqrtf(fmaxf((tot - cum[c]) * pos, 0.f));
            float eff = __expf(gneg * dist);
            eff = fminf(fmaxf(eff, 1e-5f), 1e5f);
            float v2 = vld ? sraw[c] * eff : NEG;
            p[c] = v2;
            m2 = fmaxf(m2, v2);
        }
        m2 = warpMax(m2);
        float sum2 = 0.f;
#pragma unroll
        for (int c = 0; c < 16; c++) { float e = __expf(p[c] - m2); p[c] = e; sum2 += e; }
        sum2 = warpSum(sum2);
        float inv2 = 1.0f / sum2;
#pragma unroll
        for (int c = 0; c < 16; c++) {
            int j = lane + 32 * c;
            float val = p[c] * inv2;
            bf16 hi = __float2bfloat16_rn(val);
            bf16 lo = __float2bfloat16_rn(val - __bfloat162float(hi));
            *(unsigned short*)(sm_raw + A_SS + il * 2080 + pSw + 2 * j) =
                __bfloat16_as_ushort(hi);
            *(unsigned short*)(sm_raw + A_SS + il * 2080 + 1040 + pSw + 2 * j) =
                __bfloat16_as_ushort(lo);
        }
    }
    __syncthreads();

    float acco[2][4] = {};
    for (int j0 = 0; j0 < jEnd; j0 += 128) {
#pragma unroll
        for (int i = 0; i < 4; i++) {
            int idx = tid + i * 256;
            int r = idx >> 3, s = idx & 7;
            *(uint4*)(sm_raw + AK_H + r * 144 + s * 16) =
                *(const uint4*)(Vbh + (size_t)(j0 + r) * PD + s * 8);
            *(uint4*)(sm_raw + AK_L + r * 144 + s * 16) =
                *(const uint4*)(Vbl + (size_t)(j0 + r) * PD + s * 8);
        }
        __syncthreads();
#pragma unroll
        for (int ks = 0; ks < 8; ks++) {
            uint32_t ph[2][4], pl[2][4], vh[2], vl[2];
#pragma unroll
            for (int mt = 0; mt < 2; mt++) {
                int prow = mt * 16 + aRow;
                uint32_t off = (uint32_t)(prow * 2080 + ((prow >> 2) & 1) * 16 +
                                          (j0 + ks * 16 + aCol) * 2);
                ldsm_x4(ph[mt], smb + A_SS + off);
                ldsm_x4(pl[mt], smb + A_SS + 1040 + off);
            }
            {
                uint32_t off = (uint32_t)((ks * 16 + (lane & 15)) * 144 + (w * 8) * 2);
                ldsm_x2t(vh, smb + AK_H + off);
                ldsm_x2t(vl, smb + AK_L + off);
            }
#pragma unroll
            for (int mt = 0; mt < 2; mt++) {
                mma_bf16(acco[mt], ph[mt], vh);
                mma_bf16(acco[mt], ph[mt], vl);
                mma_bf16(acco[mt], pl[mt], vh);
            }
        }
        __syncthreads();
    }

#pragma unroll
    for (int mt = 0; mt < 2; mt++) {
        int r0 = b * PS + i0 + mt * 16 + g;
        int col = h * PDK + w * 8 + 2 * t;
        uint32_t lo0, lo1;
        uint32_t h0 = split_pack(acco[mt][0], acco[mt][1], lo0);
        uint32_t h1 = split_pack(acco[mt][2], acco[mt][3], lo1);
        *(uint32_t*)(Oh + (size_t)r0 * PD + col) = h0;
        *(uint32_t*)(Ol + (size_t)r0 * PD + col) = lo0;
        *(uint32_t*)(Oh + (size_t)(r0 + 8) * PD + col) = h1;
        *(uint32_t*)(Ol + (size_t)(r0 + 8) * PD + col) = lo1;
    }
}

__global__ __launch_bounds__(256, 2) void attn_mma(
    const bf16* Qh, const bf16* Ql, const bf16* Vh, const bf16* Vl,
    const float* gammas, int layer, int strict, bf16* Oh, bf16* Ol)
{
    extern __shared__ __align__(128) char sm_raw[];
    attn_core(Qh, Ql, Vh, Vl, gammas, layer, strict, Oh, Ol, sm_raw);
}

__global__ __launch_bounds__(256, 2) void attn_dual(
    const bf16* Q0h, const bf16* Q0l, const bf16* V0h, const bf16* V0l,
    bf16* O0h, bf16* O0l,
    const bf16* Q1h, const bf16* Q1l, const bf16* V1h, const bf16* V1l,
    bf16* O1h, bf16* O1l,
    const float* gammas)
{
    extern __shared__ __align__(128) char sm_raw[];
    const int z = blockIdx.z;
    attn_core(z ? Q1h : Q0h, z ? Q1l : Q0l, z ? V1h : V0h, z ? V1l : V0l,
              gammas, z, 0, z ? O1h : O0h, z ? O1l : O0l, sm_raw);
}

// ---------------- host orchestration ----------------
static void run_gemm(int mode, const bf16* Ah, const bf16* Al,
                     const bf16* Wh, const bf16* Wl, const float* bias,
                     float* C, bf16* Ch, bf16* Cl, int Mv, int Nv, int Kv)
{
    dim3 grid(Nv / 128, Mv / 128);
    if (mode == 0)      gemm_mma<0><<<grid, 256, GEMM_SMEM>>>(Ah, Al, Wh, Wl, bias, C, Ch, Cl, Mv, Nv, Kv);
    else if (mode == 1) gemm_mma<1><<<grid, 256, GEMM_SMEM>>>(Ah, Al, Wh, Wl, bias, C, Ch, Cl, Mv, Nv, Kv);
    else                gemm_mma<2><<<grid, 256, GEMM_SMEM>>>(Ah, Al, Wh, Wl, bias, C, Ch, Cl, Mv, Nv, Kv);
}

extern "C" void kernel_launch(void* const* d_in, const int* in_sizes, int n_in,
                              void* d_out, int out_size)
{
    const float* q_embed  = (const float*)d_in[0];
    const float* qa_embed = (const float*)d_in[1];
    const float* Wk  = (const float*)d_in[2];
    const float* bk  = (const float*)d_in[3];
    const float* Wv  = (const float*)d_in[4];
    const float* bv  = (const float*)d_in[5];
    const float* Wo  = (const float*)d_in[6];
    const float* bo  = (const float*)d_in[7];
    const float* gam = (const float*)d_in[8];
    const float* l1g = (const float*)d_in[9];
    const float* l1b = (const float*)d_in[10];
    const float* W1  = (const float*)d_in[11];
    const float* b1  = (const float*)d_in[12];
    const float* W2  = (const float*)d_in[13];
    const float* b2  = (const float*)d_in[14];
    const float* l2g = (const float*)d_in[15];
    const float* l2b = (const float*)d_in[16];
    float* out = (float*)d_out;

    float *ga, *ga1, *gt, *gx;
    cudaGetSymbolAddress((void**)&ga,  g_a);
    cudaGetSymbolAddress((void**)&ga1, g_a1);
    cudaGetSymbolAddress((void**)&gt,  g_t);
    cudaGetSymbolAddress((void**)&gx,  g_x);
#define SYM(p, s) bf16* p; cudaGetSymbolAddress((void**)&p, s)
    SYM(e1h, p_e1h); SYM(e1l, p_e1l); SYM(e2h, p_e2h); SYM(e2l, p_e2l);
    SYM(qh, p_qh);   SYM(ql, p_ql);   SYM(vh, p_vh);   SYM(vl, p_vl);
    SYM(q1h, p_q1h); SYM(q1l, p_q1l); SYM(v1h, p_v1h); SYM(v1l, p_v1l);
    SYM(oh, p_oh);   SYM(ol, p_ol);   SYM(o1h, p_o1h); SYM(o1l, p_o1l);
    SYM(th, p_th);   SYM(tl, p_tl);
    SYM(yh, p_yh);   SYM(yl, p_yl);   SYM(xh, p_xh);   SYM(xl, p_xl);
    SYM(hh, p_hh);   SYM(hl, p_hl);
    SYM(wkh, p_wkh); SYM(wkl, p_wkl); SYM(wvh, p_wvh); SYM(wvl, p_wvl);
    SYM(woh, p_woh); SYM(wol, p_wol); SYM(w1h, p_w1h); SYM(w1l, p_w1l);
    SYM(w2h, p_w2h); SYM(w2l, p_w2l);
#undef SYM

    cudaFuncSetAttribute(attn_mma,  cudaFuncAttributeMaxDynamicSharedMemorySize, ATT_SMEM);
    cudaFuncSetAttribute(attn_dual, cudaFuncAttributeMaxDynamicSharedMemorySize, ATT_SMEM);
    cudaFuncSetAttribute(gemm_mma<0>, cudaFuncAttributeMaxDynamicSharedMemorySize, GEMM_SMEM);
    cudaFuncSetAttribute(gemm_mma<1>, cudaFuncAttributeMaxDynamicSharedMemorySize, GEMM_SMEM);
    cudaFuncSetAttribute(gemm_mma<2>, cudaFuncAttributeMaxDynamicSharedMemorySize, GEMM_SMEM);
    cudaFuncSetAttribute(gemm_multi<0>, cudaFuncAttributeMaxDynamicSharedMemorySize, GEMM_SMEM);
    cudaFuncSetAttribute(gemm_multi<1>, cudaFuncAttributeMaxDynamicSharedMemorySize, GEMM_SMEM);

    const size_t DD = (size_t)PD * PD, DF = (size_t)PD * PF;

    // ---- preconvert embeds + weights (one launch) ----
    {
        ConvArgs ca;
        ca.d[0] = { q_embed,  e1h, e1l, (int)((size_t)PM * PD / 4) };
        ca.d[1] = { qa_embed, e2h, e2l, (int)((size_t)PM * PD / 4) };
        ca.d[2] = { Wk, wkh, wkl, (int)(3 * DD / 4) };
        ca.d[3] = { Wv, wvh, wvl, (int)(3 * DD / 4) };
        ca.d[4] = { Wo, woh, wol, (int)(3 * DD / 4) };
        ca.d[5] = { W1, w1h, w1l, (int)(3 * DF / 4) };
        ca.d[6] = { W2, w2h, w2l, (int)(3 * DF / 4) };
        int maxn4 = (int)((size_t)PM * PD / 4);
        conv_all<<<dim3((maxn4 + 255) / 256, 7), 256>>>(ca);
    }

    // ===== Phase 1: blocks 0 & 1 fused (independent chains) =====
    {
        GSets s;
        s.s[0] = { e2h, e2l, wkh + 0 * DD, wkl + 0 * DD, bk + 0 * PD, nullptr, qh,  ql  };
        s.s[1] = { e2h, e2l, wvh + 0 * DD, wvl + 0 * DD, bv + 0 * PD, nullptr, vh,  vl  };
        s.s[2] = { e1h, e1l, wkh + 1 * DD, wkl + 1 * DD, bk + 1 * PD, nullptr, q1h, q1l };
        s.s[3] = { e1h, e1l, wvh + 1 * DD, wvl + 1 * DD, bv + 1 * PD, nullptr, v1h, v1l };
        gemm_multi<1><<<dim3(PD / 128, PM / 128, 4), 256, GEMM_SMEM>>>(s, PM, PD, PD);
    }
    attn_dual<<<dim3(PS / 32, PB * PH, 2), 256, ATT_SMEM>>>(
        qh, ql, vh, vl, oh, ol, q1h, q1l, v1h, v1l, o1h, o1l, gam);
    {
        GSets s;
        s.s[0] = { oh,  ol,  woh + 0 * DD, wol + 0 * DD, bo + 0 * PD, ga,  nullptr, nullptr };
        s.s[1] = { o1h, o1l, woh + 1 * DD, wol + 1 * DD, bo + 1 * PD, ga1, nullptr, nullptr };
        s.s[2] = s.s[0]; s.s[3] = s.s[0];
        gemm_multi<0><<<dim3(PD / 128, PM / 128, 2), 256, GEMM_SMEM>>>(s, PM, PD, PD);
    }
    add_ln_dual<<<dim3(PM / 8, 2), 256>>>(
        qa_embed, ga,  l1g + 0 * PD, l1b + 0 * PD, gt, th, tl,
        q_embed,  ga1, l1g + 1 * PD, l1b + 1 * PD, gx, xh, xl);

    // block 0 FFN
    run_gemm(2, th, tl, w1h + 0 * DF, w1l + 0 * DF, b1 + 0 * PF, nullptr, hh, hl, PM, PF, PD);
    run_gemm(0, hh, hl, w2h + 0 * DF, w2l + 0 * DF, b2 + 0 * PD, ga, nullptr, nullptr, PM, PD, PF);
    add_ln_kernel<1><<<PM / 8, 256>>>(gt, ga, l2g + 0 * PD, l2b + 0 * PD, nullptr, yh, yl);

    // ===== Block 2: knowledge retriever (q/k from x, v from y, strict mask, FFN) =====
    {
        GSets s;
        s.s[0] = { xh, xl, wkh + 2 * DD, wkl + 2 * DD, bk + 2 * PD, nullptr, qh, ql };
        s.s[1] = { yh, yl, wvh + 2 * DD, wvl + 2 * DD, bv + 2 * PD, nullptr, vh, vl };
        s.s[2] = s.s[0]; s.s[3] = s.s[0];
        gemm_multi<1><<<dim3(PD / 128, PM / 128, 2), 256, GEMM_SMEM>>>(s, PM, PD, PD);
    }
    attn_mma<<<dim3(PS / 32, PB * PH), 256, ATT_SMEM>>>(qh, ql, vh, vl, gam, 2, 1, oh, ol);
    run_gemm(0, oh, ol, woh + 2 * DD, wol + 2 * DD, bo + 2 * PD, ga, nullptr, nullptr, PM, PD, PD);
    add_ln_kernel<2><<<PM / 8, 256>>>(gx, ga, l1g + 2 * PD, l1b + 2 * PD, gt, th, tl);
    run_gemm(2, th, tl, w1h + 2 * DF, w1l + 2 * DF, b1 + 2 * PF, nullptr, hh, hl, PM, PF, PD);
    run_gemm(0, hh, hl, w2h + 2 * DF, w2l + 2 * DF, b2 + 2 * PD, ga, nullptr, nullptr, PM, PD, PF);
    add_ln_kernel<0><<<PM / 8, 256>>>(gt, ga, l2g + 2 * PD, l2b + 2 * PD, out, nullptr, nullptr);
}

// round 16
// speedup vs baseline: 1.1976x; 1.1976x over previous
#include <cuda_runtime.h>
#include <cuda_bf16.h>
#include <cuda_fp16.h>
#include <math.h>
#include <stdint.h>

// ---------------- problem constants ----------------
#define PB   16
#define PS   512
#define PD   512
#define PH   8
#define PDK  64
#define PF   2048
#define PM   (PB*PS)          // 8192 rows
#define LN_EPS 1e-5f
typedef __nv_bfloat16 bf16;
typedef __half f16;

// ---------------- scratch (device globals; no allocation) ----------------
__device__ float g_a [(size_t)PM * PD];
__device__ float g_a1[(size_t)PM * PD];
__device__ float g_t [(size_t)PM * PD];
__device__ float g_x [(size_t)PM * PD];

// activations consumed as GEMM A side: fp16 hi-plane only
__device__ f16 p_e1[(size_t)PM*PD];
__device__ f16 p_e2[(size_t)PM*PD];
__device__ f16 p_o [(size_t)PM*PD];
__device__ f16 p_o1[(size_t)PM*PD];
__device__ f16 p_t [(size_t)PM*PD];
__device__ f16 p_y [(size_t)PM*PD];
__device__ f16 p_x [(size_t)PM*PD];
__device__ f16 p_hbuf[(size_t)PM*PF];
// weights (GEMM B side): fp16 hi/lo pair
__device__ f16 p_wkh[(size_t)3*PD*PD], p_wkl[(size_t)3*PD*PD];
__device__ f16 p_wvh[(size_t)3*PD*PD], p_wvl[(size_t)3*PD*PD];
__device__ f16 p_woh[(size_t)3*PD*PD], p_wol[(size_t)3*PD*PD];
__device__ f16 p_w1h[(size_t)3*PD*PF], p_w1l[(size_t)3*PD*PF];
__device__ f16 p_w2h[(size_t)3*PF*PD], p_w2l[(size_t)3*PF*PD];
// attention q/v: bf16 hi/lo pair (attention kept at bf16x3 precision)
__device__ bf16 p_qh[(size_t)PM*PD],  p_ql[(size_t)PM*PD];
__device__ bf16 p_vh[(size_t)PM*PD],  p_vl[(size_t)PM*PD];
__device__ bf16 p_q1h[(size_t)PM*PD], p_q1l[(size_t)PM*PD];
__device__ bf16 p_v1h[(size_t)PM*PD], p_v1l[(size_t)PM*PD];

// ---------------- helpers ----------------
__device__ __forceinline__ uint32_t smem_u32(const void* p) {
    uint32_t a;
    asm("{ .reg .u64 t; cvta.to.shared.u64 t, %1; cvt.u32.u64 %0, t; }"
        : "=r"(a) : "l"(p));
    return a;
}
__device__ __forceinline__ float warpMax(float v) {
#pragma unroll
    for (int o = 16; o; o >>= 1) v = fmaxf(v, __shfl_xor_sync(0xffffffffu, v, o));
    return v;
}
__device__ __forceinline__ float warpSum(float v) {
#pragma unroll
    for (int o = 16; o; o >>= 1) v += __shfl_xor_sync(0xffffffffu, v, o);
    return v;
}
// bf16 split (attention path)
__device__ __forceinline__ uint32_t split_pack(float x, float y, uint32_t& lo_pack) {
    bf16 hx = __float2bfloat16_rn(x);
    bf16 hy = __float2bfloat16_rn(y);
    bf16 lx = __float2bfloat16_rn(x - __bfloat162float(hx));
    bf16 ly = __float2bfloat16_rn(y - __bfloat162float(hy));
    lo_pack = ((uint32_t)__bfloat16_as_ushort(ly) << 16) | (uint32_t)__bfloat16_as_ushort(lx);
    return ((uint32_t)__bfloat16_as_ushort(hy) << 16) | (uint32_t)__bfloat16_as_ushort(hx);
}
// fp16 split (GEMM path)
__device__ __forceinline__ uint32_t hsplit_pack(float x, float y, uint32_t& lo_pack) {
    f16 hx = __float2half_rn(x);
    f16 hy = __float2half_rn(y);
    f16 lx = __float2half_rn(x - __half2float(hx));
    f16 ly = __float2half_rn(y - __half2float(hy));
    lo_pack = ((uint32_t)__half_as_ushort(ly) << 16) | (uint32_t)__half_as_ushort(lx);
    return ((uint32_t)__half_as_ushort(hy) << 16) | (uint32_t)__half_as_ushort(hx);
}
__device__ __forceinline__ uint32_t hpack(float x, float y) {
    return ((uint32_t)__half_as_ushort(__float2half_rn(y)) << 16) |
           (uint32_t)__half_as_ushort(__float2half_rn(x));
}
__device__ __forceinline__ void ldsm_x4(uint32_t* r, uint32_t addr) {
    asm volatile("ldmatrix.sync.aligned.m8n8.x4.shared.b16 {%0,%1,%2,%3}, [%4];"
                 : "=r"(r[0]), "=r"(r[1]), "=r"(r[2]), "=r"(r[3]) : "r"(addr));
}
__device__ __forceinline__ void ldsm_x2(uint32_t* r, uint32_t addr) {
    asm volatile("ldmatrix.sync.aligned.m8n8.x2.shared.b16 {%0,%1}, [%2];"
                 : "=r"(r[0]), "=r"(r[1]) : "r"(addr));
}
__device__ __forceinline__ void ldsm_x2t(uint32_t* r, uint32_t addr) {
    asm volatile("ldmatrix.sync.aligned.m8n8.x2.trans.shared.b16 {%0,%1}, [%2];"
                 : "=r"(r[0]), "=r"(r[1]) : "r"(addr));
}
__device__ __forceinline__ void mma_bf16(float c[4], const uint32_t a[4], const uint32_t b[2]) {
    asm volatile(
        "mma.sync.aligned.m16n8k16.row.col.f32.bf16.bf16.f32 "
        "{%0,%1,%2,%3}, {%4,%5,%6,%7}, {%8,%9}, {%0,%1,%2,%3};"
        : "+f"(c[0]), "+f"(c[1]), "+f"(c[2]), "+f"(c[3])
        : "r"(a[0]), "r"(a[1]), "r"(a[2]), "r"(a[3]), "r"(b[0]), "r"(b[1]));
}
__device__ __forceinline__ void mma_f16(float c[4], const uint32_t a[4], const uint32_t b[2]) {
    asm volatile(
        "mma.sync.aligned.m16n8k16.row.col.f32.f16.f16.f32 "
        "{%0,%1,%2,%3}, {%4,%5,%6,%7}, {%8,%9}, {%0,%1,%2,%3};"
        : "+f"(c[0]), "+f"(c[1]), "+f"(c[2]), "+f"(c[3])
        : "r"(a[0]), "r"(a[1]), "r"(a[2]), "r"(a[3]), "r"(b[0]), "r"(b[1]));
}
__device__ __forceinline__ void cp16(uint32_t dst, const void* src) {
    asm volatile("cp.async.cg.shared.global [%0], [%1], 16;"
                 :: "r"(dst), "l"(src) : "memory");
}
#define CP_COMMIT() asm volatile("cp.async.commit_group;" ::: "memory")
#define CP_WAIT1()  asm volatile("cp.async.wait_group 1;" ::: "memory")
#define CP_WAIT0()  asm volatile("cp.async.wait_group 0;" ::: "memory")

// ---------------- fp32 -> fp16 hi(/lo) conversion (all tensors, one launch) ----------------
struct ConvDesc { const float* s; f16* h; f16* l; int n4; };
struct ConvArgs { ConvDesc d[7]; };

__global__ __launch_bounds__(256) void conv_all(ConvArgs a)
{
    ConvDesc d = a.d[blockIdx.y];
    int i = blockIdx.x * 256 + threadIdx.x;
    if (i < d.n4) {
        float4 v = ((const float4*)d.s)[i];
        uint32_t lo0, lo1;
        uint32_t h0 = hsplit_pack(v.x, v.y, lo0);
        uint32_t h1 = hsplit_pack(v.z, v.w, lo1);
        ((uint2*)d.h)[i] = make_uint2(h0, h1);
        if (d.l) ((uint2*)d.l)[i] = make_uint2(lo0, lo1);
    }
}

// ======================= fp16x2 tensor-core GEMM (cp.async) =======================
// C[M,N] = A[M,K] @ W[K,N] + bias. A: fp16 hi-plane; W: fp16 hi/lo pair.
// D = Ahi*Whi + Ahi*Wlo (2 MMAs/tile). Tile 128x128, K-chunk 32, 2-stage, 2 CTAs/SM.
// OUTMODE: 0 = fp32, 1 = bf16 pair (attention q/v), 2 = fp16 hi + ReLU (FFN hidden).
#define SA    0
#define SB_HI 10240
#define SB_LO 18944
#define STAGE 27648
#define GEMM_SMEM (2 * STAGE)

template <int OUTMODE>
__device__ __forceinline__ void gemm_core(
    const f16* __restrict__ A,
    const f16* __restrict__ Wh, const f16* __restrict__ Wl,
    const float* __restrict__ bias,
    float* __restrict__ C, bf16* __restrict__ Ch, bf16* __restrict__ Cl,
    f16* __restrict__ Hh,
    int Mv, int Nv, int Kv, char* smem_raw)
{
    const uint32_t smb = smem_u32(smem_raw);
    const int tid = threadIdx.x;
    const int lane = tid & 31;
    const int wid = tid >> 5;
    const int wm = (wid >> 2) * 64;
    const int wn = (wid & 3) * 32;
    const int by = blockIdx.y * 128;
    const int bx = blockIdx.x * 128;
    const int nC = Kv >> 5;

    float c[4][4][4] = {};
    const int aRow = (lane & 7) + ((lane >> 3) & 1) * 8;
    const int aCol = (lane >> 4) * 8;
    const int bRow = lane & 15;

    auto issue = [&](int ck) {
        const uint32_t sb = smb + (ck & 1) * STAGE;
        const int k0 = ck * 32;
#pragma unroll
        for (int i = 0; i < 2; i++) {               // A: 128 rows x 64B (hi only)
            int idx = tid + i * 256;
            int r = idx >> 2, s = idx & 3;
            cp16(sb + SA + r * 80 + s * 16, A + (size_t)(by + r) * Kv + k0 + s * 8);
        }
#pragma unroll
        for (int i = 0; i < 2; i++) {               // B: 32 rows x 256B per plane
            int idx = tid + i * 256;
            int r = idx >> 4, s = idx & 15;
            size_t go = (size_t)(k0 + r) * Nv + bx + s * 8;
            cp16(sb + SB_HI + r * 272 + s * 16, Wh + go);
            cp16(sb + SB_LO + r * 272 + s * 16, Wl + go);
        }
        CP_COMMIT();
    };

    issue(0);

    for (int ck = 0; ck < nC; ck++) {
        if (ck + 1 < nC) { issue(ck + 1); CP_WAIT1(); }
        else             { CP_WAIT0(); }
        __syncthreads();

        const uint32_t sb = smb + (ck & 1) * STAGE;
#pragma unroll
        for (int ks = 0; ks < 32; ks += 16) {
            uint32_t ah[4][4], bh[4][2], bl[4][2];
#pragma unroll
            for (int mt = 0; mt < 4; mt++) {
                uint32_t off = (uint32_t)((wm + mt * 16 + aRow) * 80 + (ks + aCol) * 2);
                ldsm_x4(ah[mt], sb + SA + off);
            }
#pragma unroll
            for (int nt = 0; nt < 4; nt++) {
                uint32_t off = (uint32_t)((ks + bRow) * 272 + (wn + nt * 8) * 2);
                ldsm_x2t(bh[nt], sb + SB_HI + off);
                ldsm_x2t(bl[nt], sb + SB_LO + off);
            }
#pragma unroll
            for (int mt = 0; mt < 4; mt++)
#pragma unroll
                for (int nt = 0; nt < 4; nt++) {
                    mma_f16(c[mt][nt], ah[mt], bh[nt]);
                    mma_f16(c[mt][nt], ah[mt], bl[nt]);
                }
        }
        __syncthreads();
    }

    const int g = lane >> 2, t = lane & 3;
#pragma unroll
    for (int mt = 0; mt < 4; mt++) {
#pragma unroll
        for (int nt = 0; nt < 4; nt++) {
            int row = by + wm + mt * 16 + g;
            int col = bx + wn + nt * 8 + 2 * t;
            float2 bv = *(const float2*)(bias + col);
            float v00 = c[mt][nt][0] + bv.x, v01 = c[mt][nt][1] + bv.y;
            float v10 = c[mt][nt][2] + bv.x, v11 = c[mt][nt][3] + bv.y;
            if (OUTMODE == 2) {
                v00 = fmaxf(v00, 0.f); v01 = fmaxf(v01, 0.f);
                v10 = fmaxf(v10, 0.f); v11 = fmaxf(v11, 0.f);
            }
            if (OUTMODE == 0) {
                *(float2*)(C + (size_t)row * Nv + col) = make_float2(v00, v01);
                *(float2*)(C + (size_t)(row + 8) * Nv + col) = make_float2(v10, v11);
            } else if (OUTMODE == 1) {
                uint32_t lo0, lo1;
                uint32_t h0 = split_pack(v00, v01, lo0);
                uint32_t h1 = split_pack(v10, v11, lo1);
                *(uint32_t*)(Ch + (size_t)row * Nv + col) = h0;
                *(uint32_t*)(Cl + (size_t)row * Nv + col) = lo0;
                *(uint32_t*)(Ch + (size_t)(row + 8) * Nv + col) = h1;
                *(uint32_t*)(Cl + (size_t)(row + 8) * Nv + col) = lo1;
            } else {
                *(uint32_t*)(Hh + (size_t)row * Nv + col) = hpack(v00, v01);
                *(uint32_t*)(Hh + (size_t)(row + 8) * Nv + col) = hpack(v10, v11);
            }
        }
    }
}

template <int OUTMODE>
__global__ __launch_bounds__(256, 2)
void gemm_mma(const f16* __restrict__ A,
              const f16* __restrict__ Wh, const f16* __restrict__ Wl,
              const float* __restrict__ bias,
              float* __restrict__ C, bf16* __restrict__ Ch, bf16* __restrict__ Cl,
              f16* __restrict__ Hh, int Mv, int Nv, int Kv)
{
    extern __shared__ __align__(128) char smem_raw[];
    gemm_core<OUTMODE>(A, Wh, Wl, bias, C, Ch, Cl, Hh, Mv, Nv, Kv, smem_raw);
}

// multi-set GEMM: blockIdx.z selects pointer set
struct GSet  { const f16 *A, *Wh, *Wl; const float* bias; float* C; bf16 *Ch, *Cl; f16* Hh; };
struct GSets { GSet s[4]; };

template <int OUTMODE>
__global__ __launch_bounds__(256, 2)
void gemm_multi(GSets sets, int Mv, int Nv, int Kv)
{
    extern __shared__ __align__(128) char smem_raw[];
    GSet g = sets.s[blockIdx.z];
    gemm_core<OUTMODE>(g.A, g.Wh, g.Wl, g.bias, g.C, g.Ch, g.Cl, g.Hh,
                       Mv, Nv, Kv, smem_raw);
}

// ---------------- fused add + LayerNorm (warp-per-row) ----------------
// MODE: 0 = fp32 only, 1 = fp16 hi only, 2 = fp32 + fp16 hi
template <int MODE>
__device__ __forceinline__ void add_ln_row(
    int row,
    const float* __restrict__ A, const float* __restrict__ Bv,
    const float* __restrict__ g, const float* __restrict__ be,
    float* __restrict__ outF, f16* __restrict__ outH)
{
    const int lane = threadIdx.x & 31;
    float4 x4[4];
    float sum = 0.f;
#pragma unroll
    for (int i = 0; i < 4; i++) {
        int idx = lane + i * 32;
        float4 xa = ((const float4*)(A  + (size_t)row * PD))[idx];
        float4 xb = ((const float4*)(Bv + (size_t)row * PD))[idx];
        x4[i].x = xa.x + xb.x; x4[i].y = xa.y + xb.y;
        x4[i].z = xa.z + xb.z; x4[i].w = xa.w + xb.w;
        sum += x4[i].x + x4[i].y + x4[i].z + x4[i].w;
    }
    float mean = warpSum(sum) * (1.0f / PD);
    float vs = 0.f;
#pragma unroll
    for (int i = 0; i < 4; i++) {
        x4[i].x -= mean; x4[i].y -= mean; x4[i].z -= mean; x4[i].w -= mean;
        vs += x4[i].x * x4[i].x + x4[i].y * x4[i].y +
              x4[i].z * x4[i].z + x4[i].w * x4[i].w;
    }
    float rstd = rsqrtf(warpSum(vs) * (1.0f / PD) + LN_EPS);
#pragma unroll
    for (int i = 0; i < 4; i++) {
        int idx = lane + i * 32;
        float4 gg = ((const float4*)g)[idx];
        float4 bb = ((const float4*)be)[idx];
        float o0 = x4[i].x * rstd * gg.x + bb.x;
        float o1 = x4[i].y * rstd * gg.y + bb.y;
        float o2 = x4[i].z * rstd * gg.z + bb.z;
        float o3 = x4[i].w * rstd * gg.w + bb.w;
        if (MODE != 1)
            ((float4*)(outF + (size_t)row * PD))[idx] = make_float4(o0, o1, o2, o3);
        if (MODE != 0)
            ((uint2*)(outH + (size_t)row * PD))[idx] =
                make_uint2(hpack(o0, o1), hpack(o2, o3));
    }
}

template <int MODE>
__global__ __launch_bounds__(256) void add_ln_kernel(
    const float* __restrict__ A, const float* __restrict__ Bv,
    const float* __restrict__ g, const float* __restrict__ be,
    float* __restrict__ outF, f16* __restrict__ outH)
{
    int row = blockIdx.x * 8 + (threadIdx.x >> 5);
    add_ln_row<MODE>(row, A, Bv, g, be, outF, outH);
}

__global__ __launch_bounds__(256) void add_ln_dual(
    const float* A0, const float* B0, const float* g0, const float* be0,
    float* f0, f16* h0,
    const float* A1, const float* B1, const float* g1, const float* be1,
    float* f1, f16* h1)
{
    int row = blockIdx.x * 8 + (threadIdx.x >> 5);
    if (blockIdx.y == 0)
        add_ln_row<2>(row, A0, B0, g0, be0, f0, h0);
    else
        add_ln_row<2>(row, A1, B1, g1, be1, f1, h1);
}

// ---------------- fused distance-decay attention (bf16x3, unchanged core) ----------------
#define AQ_H 0
#define AQ_L 4608
#define AK_H 9216
#define AK_L 27648
#define A_SS 46080
#define ATT_SMEM 112640

__device__ __forceinline__ void attn_core(
    const bf16* __restrict__ Qh, const bf16* __restrict__ Ql,
    const bf16* __restrict__ Vh, const bf16* __restrict__ Vl,
    const float* __restrict__ gammas, int layer, int strict,
    f16* __restrict__ O, char* sm_raw)
{
    const uint32_t smb = smem_u32(sm_raw);
    float* sS = (float*)(sm_raw + A_SS);

    const int bh = blockIdx.y;
    const int b = bh >> 3, h = bh & 7;
    const int i0 = blockIdx.x * 32;
    const int tid = threadIdx.x;
    const int lane = tid & 31, w = tid >> 5;

    int nCh = (i0 + 32 + 127) >> 7;
    if (strict && i0 == 0) nCh = 4;
    const int jEnd = nCh * 128;

    float gamma = gammas[layer * PH + h];
    float gneg = (gamma > 20.f) ? -gamma : -log1pf(expf(gamma));

    const size_t headOff = (size_t)(b * PS) * PD + h * PDK;
    const bf16* Qbh = Qh + headOff;
    const bf16* Qbl = Ql + headOff;
    const bf16* Vbh = Vh + headOff;
    const bf16* Vbl = Vl + headOff;

    const int aRow = (lane & 7) + ((lane >> 3) & 1) * 8;
    const int aCol = (lane >> 4) * 8;
    const int g = lane >> 2, t = lane & 3;

    {
        int r = tid >> 3, s = tid & 7;
        *(uint4*)(sm_raw + AQ_H + r * 144 + s * 16) =
            *(const uint4*)(Qbh + (size_t)(i0 + r) * PD + s * 8);
        *(uint4*)(sm_raw + AQ_L + r * 144 + s * 16) =
            *(const uint4*)(Qbl + (size_t)(i0 + r) * PD + s * 8);
    }

    for (int j0 = 0; j0 < jEnd; j0 += 128) {
#pragma unroll
        for (int i = 0; i < 4; i++) {
            int idx = tid + i * 256;
            int r = idx >> 3, s = idx & 7;
            *(uint4*)(sm_raw + AK_H + r * 144 + s * 16) =
                *(const uint4*)(Qbh + (size_t)(j0 + r) * PD + s * 8);
            *(uint4*)(sm_raw + AK_L + r * 144 + s * 16) =
                *(const uint4*)(Qbl + (size_t)(j0 + r) * PD + s * 8);
        }
        __syncthreads();

        float acc[2][2][4] = {};
#pragma unroll
        for (int ks = 0; ks < 64; ks += 16) {
            uint32_t ah[2][4], al[2][4], kh[2][2], kl[2][2];
#pragma unroll
            for (int mt = 0; mt < 2; mt++) {
                uint32_t off = (uint32_t)((mt * 16 + aRow) * 144 + (ks + aCol) * 2);
                ldsm_x4(ah[mt], smb + AQ_H + off);
                ldsm_x4(al[mt], smb + AQ_L + off);
            }
#pragma unroll
            for (int nf = 0; nf < 2; nf++) {
                uint32_t off = (uint32_t)((w * 16 + nf * 8 + (lane & 7)) * 144 +
                                          (ks + ((lane >> 3) & 1) * 8) * 2);
                ldsm_x2(kh[nf], smb + AK_H + off);
                ldsm_x2(kl[nf], smb + AK_L + off);
            }
#pragma unroll
            for (int mt = 0; mt < 2; mt++)
#pragma unroll
                for (int nf = 0; nf < 2; nf++) {
                    mma_bf16(acc[mt][nf], ah[mt], kh[nf]);
                    mma_bf16(acc[mt][nf], ah[mt], kl[nf]);
                    mma_bf16(acc[mt][nf], al[mt], kh[nf]);
                }
        }
        const float scale = 0.125f;
#pragma unroll
        for (int mt = 0; mt < 2; mt++)
#pragma unroll
            for (int nf = 0; nf < 2; nf++) {
                int r0 = mt * 16 + g;
                int col = j0 + w * 16 + nf * 8 + 2 * t;
                *(float2*)&sS[r0 * 520 + col] =
                    make_float2(acc[mt][nf][0] * scale, acc[mt][nf][1] * scale);
                *(float2*)&sS[(r0 + 8) * 520 + col] =
                    make_float2(acc[mt][nf][2] * scale, acc[mt][nf][3] * scale);
            }
        __syncthreads();
    }

    const float NEG = -1e32f;
    for (int rr = 0; rr < 4; rr++) {
        const int il = w + rr * 8;
        const int ig = i0 + il;
        const uint32_t pSw = (uint32_t)(((il >> 2) & 1) * 16);
        float sraw[16], p[16], cum[16];
        float mx = NEG;
#pragma unroll
        for (int c = 0; c < 16; c++) {
            int j = lane + 32 * c;
            sraw[c] = sS[il * 520 + j];
            bool vld = strict ? (j < ig) : (j <= ig);
            float s1 = vld ? sraw[c] : NEG;
            p[c] = s1;
            mx = fmaxf(mx, s1);
        }
        mx = warpMax(mx);
        float sum = 0.f;
#pragma unroll
        for (int c = 0; c < 16; c++) { float e = __expf(p[c] - mx); p[c] = e; sum += e; }
        sum = warpSum(sum);
        float inv = 1.0f / sum;
#pragma unroll
        for (int c = 0; c < 16; c++) {
            int j = lane + 32 * c;
            bool vld = strict ? (j < ig) : (j <= ig);
            p[c] = vld ? p[c] * inv : 0.f;
        }
        float run = 0.f;
#pragma unroll
        for (int c = 0; c < 16; c++) {
            float sc = p[c];
#pragma unroll
            for (int o = 1; o < 32; o <<= 1) {
                float tt = __shfl_up_sync(0xffffffffu, sc, o);
                if (lane >= o) sc += tt;
            }
            cum[c] = run + sc;
            run += __shfl_sync(0xffffffffu, sc, 31);
        }
        const float tot = run;
        float m2 = NEG;
#pragma unroll
        for (int c = 0; c < 16; c++) {
            int j = lane + 32 * c;
            bool vld = strict ? (j < ig) : (j <= ig);
            float pos = fabsf((float)(ig - j));
            float dist = sqrtf(fmaxf((tot - cum[c]) * pos, 0.f));
            float eff = __expf(gneg * dist);
            eff = fminf(fmaxf(eff, 1e-5f), 1e5f);
            float v2 = vld ? sraw[c] * eff : NEG;
            p[c] = v2;
            m2 = fmaxf(m2, v2);
        }
        m2 = warpMax(m2);
        float sum2 = 0.f;
#pragma unroll
        for (int c = 0; c < 16; c++) { float e = __expf(p[c] - m2); p[c] = e; sum2 += e; }
        sum2 = warpSum(sum2);
        float inv2 = 1.0f / sum2;
#pragma unroll
        for (int c = 0; c < 16; c++) {
            int j = lane + 32 * c;
            float val = p[c] * inv2;
            bf16 hi = __float2bfloat16_rn(val);
            bf16 lo = __float2bfloat16_rn(val - __bfloat162float(hi));
            *(unsigned short*)(sm_raw + A_SS + il * 2080 + pSw + 2 * j) =
                __bfloat16_as_ushort(hi);
            *(unsigned short*)(sm_raw + A_SS + il * 2080 + 1040 + pSw + 2 * j) =
                __bfloat16_as_ushort(lo);
        }
    }
    __syncthreads();

    float acco[2][4] = {};
    for (int j0 = 0; j0 < jEnd; j0 += 128) {
#pragma unroll
        for (int i = 0; i < 4; i++) {
            int idx = tid + i * 256;
            int r = idx >> 3, s = idx & 7;
            *(uint4*)(sm_raw + AK_H + r * 144 + s * 16) =
                *(const uint4*)(Vbh + (size_t)(j0 + r) * PD + s * 8);
            *(uint4*)(sm_raw + AK_L + r * 144 + s * 16) =
                *(const uint4*)(Vbl + (size_t)(j0 + r) * PD + s * 8);
        }
        __syncthreads();
#pragma unroll
        for (int ks = 0; ks < 8; ks++) {
            uint32_t ph[2][4], pl[2][4], vh[2], vl[2];
#pragma unroll
            for (int mt = 0; mt < 2; mt++) {
                int prow = mt * 16 + aRow;
                uint32_t off = (uint32_t)(prow * 2080 + ((prow >> 2) & 1) * 16 +
                                          (j0 + ks * 16 + aCol) * 2);
                ldsm_x4(ph[mt], smb + A_SS + off);
                ldsm_x4(pl[mt], smb + A_SS + 1040 + off);
            }
            {
                uint32_t off = (uint32_t)((ks * 16 + (lane & 15)) * 144 + (w * 8) * 2);
                ldsm_x2t(vh, smb + AK_H + off);
                ldsm_x2t(vl, smb + AK_L + off);
            }
#pragma unroll
            for (int mt = 0; mt < 2; mt++) {
                mma_bf16(acco[mt], ph[mt], vh);
                mma_bf16(acco[mt], ph[mt], vl);
                mma_bf16(acco[mt], pl[mt], vh);
            }
        }
        __syncthreads();
    }

    // ---- write O as fp16 hi plane (A side of Wo GEMM) ----
#pragma unroll
    for (int mt = 0; mt < 2; mt++) {
        int r0 = b * PS + i0 + mt * 16 + g;
        int col = h * PDK + w * 8 + 2 * t;
        *(uint32_t*)(O + (size_t)r0 * PD + col) = hpack(acco[mt][0], acco[mt][1]);
        *(uint32_t*)(O + (size_t)(r0 + 8) * PD + col) = hpack(acco[mt][2], acco[mt][3]);
    }
}

__global__ __launch_bounds__(256, 2) void attn_mma(
    const bf16* Qh, const bf16* Ql, const bf16* Vh, const bf16* Vl,
    const float* gammas, int layer, int strict, f16* O)
{
    extern __shared__ __align__(128) char sm_raw[];
    attn_core(Qh, Ql, Vh, Vl, gammas, layer, strict, O, sm_raw);
}

__global__ __launch_bounds__(256, 2) void attn_dual(
    const bf16* Q0h, const bf16* Q0l, const bf16* V0h, const bf16* V0l, f16* O0,
    const bf16* Q1h, const bf16* Q1l, const bf16* V1h, const bf16* V1l, f16* O1,
    const float* gammas)
{
    extern __shared__ __align__(128) char sm_raw[];
    const int z = blockIdx.z;
    attn_core(z ? Q1h : Q0h, z ? Q1l : Q0l, z ? V1h : V0h, z ? V1l : V0l,
              gammas, z, 0, z ? O1 : O0, sm_raw);
}

// ---------------- host orchestration ----------------
static void run_gemm(int mode, const f16* A, const f16* Wh, const f16* Wl,
                     const float* bias, float* C, bf16* Ch, bf16* Cl, f16* Hh,
                     int Mv, int Nv, int Kv)
{
    dim3 grid(Nv / 128, Mv / 128);
    if (mode == 0)      gemm_mma<0><<<grid, 256, GEMM_SMEM>>>(A, Wh, Wl, bias, C, Ch, Cl, Hh, Mv, Nv, Kv);
    else if (mode == 1) gemm_mma<1><<<grid, 256, GEMM_SMEM>>>(A, Wh, Wl, bias, C, Ch, Cl, Hh, Mv, Nv, Kv);
    else                gemm_mma<2><<<grid, 256, GEMM_SMEM>>>(A, Wh, Wl, bias, C, Ch, Cl, Hh, Mv, Nv, Kv);
}

extern "C" void kernel_launch(void* const* d_in, const int* in_sizes, int n_in,
                              void* d_out, int out_size)
{
    const float* q_embed  = (const float*)d_in[0];
    const float* qa_embed = (const float*)d_in[1];
    const float* Wk  = (const float*)d_in[2];
    const float* bk  = (const float*)d_in[3];
    const float* Wv  = (const float*)d_in[4];
    const float* bv  = (const float*)d_in[5];
    const float* Wo  = (const float*)d_in[6];
    const float* bo  = (const float*)d_in[7];
    const float* gam = (const float*)d_in[8];
    const float* l1g = (const float*)d_in[9];
    const float* l1b = (const float*)d_in[10];
    const float* W1  = (const float*)d_in[11];
    const float* b1  = (const float*)d_in[12];
    const float* W2  = (const float*)d_in[13];
    const float* b2  = (const float*)d_in[14];
    const float* l2g = (const float*)d_in[15];
    const float* l2b = (const float*)d_in[16];
    float* out = (float*)d_out;

    float *ga, *ga1, *gt, *gx;
    cudaGetSymbolAddress((void**)&ga,  g_a);
    cudaGetSymbolAddress((void**)&ga1, g_a1);
    cudaGetSymbolAddress((void**)&gt,  g_t);
    cudaGetSymbolAddress((void**)&gx,  g_x);
#define SYMH(p, s) f16* p; cudaGetSymbolAddress((void**)&p, s)
#define SYMB(p, s) bf16* p; cudaGetSymbolAddress((void**)&p, s)
    SYMH(e1, p_e1); SYMH(e2, p_e2);
    SYMH(po, p_o);  SYMH(po1, p_o1);
    SYMH(pt, p_t);  SYMH(py, p_y);  SYMH(px, p_x);  SYMH(ph, p_hbuf);
    SYMH(wkh, p_wkh); SYMH(wkl, p_wkl); SYMH(wvh, p_wvh); SYMH(wvl, p_wvl);
    SYMH(woh, p_woh); SYMH(wol, p_wol); SYMH(w1h, p_w1h); SYMH(w1l, p_w1l);
    SYMH(w2h, p_w2h); SYMH(w2l, p_w2l);
    SYMB(qh, p_qh);   SYMB(ql, p_ql);   SYMB(vh, p_vh);   SYMB(vl, p_vl);
    SYMB(q1h, p_q1h); SYMB(q1l, p_q1l); SYMB(v1h, p_v1h); SYMB(v1l, p_v1l);
#undef SYMH
#undef SYMB

    cudaFuncSetAttribute(attn_mma,  cudaFuncAttributeMaxDynamicSharedMemorySize, ATT_SMEM);
    cudaFuncSetAttribute(attn_dual, cudaFuncAttributeMaxDynamicSharedMemorySize, ATT_SMEM);
    cudaFuncSetAttribute(gemm_mma<0>, cudaFuncAttributeMaxDynamicSharedMemorySize, GEMM_SMEM);
    cudaFuncSetAttribute(gemm_mma<1>, cudaFuncAttributeMaxDynamicSharedMemorySize, GEMM_SMEM);
    cudaFuncSetAttribute(gemm_mma<2>, cudaFuncAttributeMaxDynamicSharedMemorySize, GEMM_SMEM);
    cudaFuncSetAttribute(gemm_multi<0>, cudaFuncAttributeMaxDynamicSharedMemorySize, GEMM_SMEM);
    cudaFuncSetAttribute(gemm_multi<1>, cudaFuncAttributeMaxDynamicSharedMemorySize, GEMM_SMEM);

    const size_t DD = (size_t)PD * PD, DF = (size_t)PD * PF;

    // ---- preconvert: embeds hi-only, weights hi/lo pair ----
    {
        ConvArgs ca;
        ca.d[0] = { q_embed,  e1, nullptr, (int)((size_t)PM * PD / 4) };
        ca.d[1] = { qa_embed, e2, nullptr, (int)((size_t)PM * PD / 4) };
        ca.d[2] = { Wk, wkh, wkl, (int)(3 * DD / 4) };
        ca.d[3] = { Wv, wvh, wvl, (int)(3 * DD / 4) };
        ca.d[4] = { Wo, woh, wol, (int)(3 * DD / 4) };
        ca.d[5] = { W1, w1h, w1l, (int)(3 * DF / 4) };
        ca.d[6] = { W2, w2h, w2l, (int)(3 * DF / 4) };
        int maxn4 = (int)((size_t)PM * PD / 4);
        conv_all<<<dim3((maxn4 + 255) / 256, 7), 256>>>(ca);
    }

    // ===== Phase 1: blocks 0 & 1 fused (independent chains) =====
    {
        GSets s;
        s.s[0] = { e2, wkh + 0 * DD, wkl + 0 * DD, bk + 0 * PD, nullptr, qh,  ql,  nullptr };
        s.s[1] = { e2, wvh + 0 * DD, wvl + 0 * DD, bv + 0 * PD, nullptr, vh,  vl,  nullptr };
        s.s[2] = { e1, wkh + 1 * DD, wkl + 1 * DD, bk + 1 * PD, nullptr, q1h, q1l, nullptr };
        s.s[3] = { e1, wvh + 1 * DD, wvl + 1 * DD, bv + 1 * PD, nullptr, v1h, v1l, nullptr };
        gemm_multi<1><<<dim3(PD / 128, PM / 128, 4), 256, GEMM_SMEM>>>(s, PM, PD, PD);
    }
    attn_dual<<<dim3(PS / 32, PB * PH, 2), 256, ATT_SMEM>>>(
        qh, ql, vh, vl, po, q1h, q1l, v1h, v1l, po1, gam);
    {
        GSets s;
        s.s[0] = { po,  woh + 0 * DD, wol + 0 * DD, bo + 0 * PD, ga,  nullptr, nullptr, nullptr };
        s.s[1] = { po1, woh + 1 * DD, wol + 1 * DD, bo + 1 * PD, ga1, nullptr, nullptr, nullptr };
        s.s[2] = s.s[0]; s.s[3] = s.s[0];
        gemm_multi<0><<<dim3(PD / 128, PM / 128, 2), 256, GEMM_SMEM>>>(s, PM, PD, PD);
    }
    add_ln_dual<<<dim3(PM / 8, 2), 256>>>(
        qa_embed, ga,  l1g + 0 * PD, l1b + 0 * PD, gt, pt,
        q_embed,  ga1, l1g + 1 * PD, l1b + 1 * PD, gx, px);

    // block 0 FFN
    run_gemm(2, pt, w1h + 0 * DF, w1l + 0 * DF, b1 + 0 * PF, nullptr, nullptr, nullptr, ph, PM, PF, PD);
    run_gemm(0, ph, w2h + 0 * DF, w2l + 0 * DF, b2 + 0 * PD, ga, nullptr, nullptr, nullptr, PM, PD, PF);
    add_ln_kernel<1><<<PM / 8, 256>>>(gt, ga, l2g + 0 * PD, l2b + 0 * PD, nullptr, py);

    // ===== Block 2: knowledge retriever (q/k from x, v from y, strict mask, FFN) =====
    {
        GSets s;
        s.s[0] = { px, wkh + 2 * DD, wkl + 2 * DD, bk + 2 * PD, nullptr, qh, ql, nullptr };
        s.s[1] = { py, wvh + 2 * DD, wvl + 2 * DD, bv + 2 * PD, nullptr, vh, vl, nullptr };
        s.s[2] = s.s[0]; s.s[3] = s.s[0];
        gemm_multi<1><<<dim3(PD / 128, PM / 128, 2), 256, GEMM_SMEM>>>(s, PM, PD, PD);
    }
    attn_mma<<<dim3(PS / 32, PB * PH), 256, ATT_SMEM>>>(qh, ql, vh, vl, gam, 2, 1, po);
    run_gemm(0, po, woh + 2 * DD, wol + 2 * DD, bo + 2 * PD, ga, nullptr, nullptr, nullptr, PM, PD, PD);
    add_ln_kernel<2><<<PM / 8, 256>>>(gx, ga, l1g + 2 * PD, l1b + 2 * PD, gt, pt);
    run_gemm(2, pt, w1h + 2 * DF, w1l + 2 * DF, b1 + 2 * PF, nullptr, nullptr, nullptr, ph, PM, PF, PD);
    run_gemm(0, ph, w2h + 2 * DF, w2l + 2 * DF, b2 + 2 * PD, ga, nullptr, nullptr, nullptr, PM, PD, PF);
    add_ln_kernel<0><<<PM / 8, 256>>>(gt, ga, l2g + 2 * PD, l2b + 2 * PD, out, nullptr);
}

// round 17
// speedup vs baseline: 1.4918x; 1.2456x over previous
#include <cuda_runtime.h>
#include <cuda_bf16.h>
#include <cuda_fp16.h>
#include <math.h>
#include <stdint.h>

// ---------------- problem constants ----------------
#define PB   16
#define PS   512
#define PD   512
#define PH   8
#define PDK  64
#define PF   2048
#define PM   (PB*PS)          // 8192 rows
#define LN_EPS 1e-5f
typedef __nv_bfloat16 bf16;
typedef __half f16;

// ---------------- scratch (device globals; no allocation) ----------------
__device__ float g_a [(size_t)PM * PD];
__device__ float g_a1[(size_t)PM * PD];
__device__ float g_t [(size_t)PM * PD];
__device__ float g_x [(size_t)PM * PD];

// activations consumed as GEMM A side: fp16 hi-plane only
__device__ f16 p_e1[(size_t)PM*PD];
__device__ f16 p_e2[(size_t)PM*PD];
__device__ f16 p_o [(size_t)PM*PD];
__device__ f16 p_o1[(size_t)PM*PD];
__device__ f16 p_t [(size_t)PM*PD];
__device__ f16 p_y [(size_t)PM*PD];
__device__ f16 p_x [(size_t)PM*PD];
__device__ f16 p_hbuf[(size_t)PM*PF];
// weights (GEMM B side): fp16 single plane
__device__ f16 p_wk[(size_t)3*PD*PD];
__device__ f16 p_wv[(size_t)3*PD*PD];
__device__ f16 p_wo[(size_t)3*PD*PD];
__device__ f16 p_w1[(size_t)3*PD*PF];
__device__ f16 p_w2[(size_t)3*PF*PD];
// attention q/v: bf16 hi/lo pair (attention kept at bf16x3 precision)
__device__ bf16 p_qh[(size_t)PM*PD],  p_ql[(size_t)PM*PD];
__device__ bf16 p_vh[(size_t)PM*PD],  p_vl[(size_t)PM*PD];
__device__ bf16 p_q1h[(size_t)PM*PD], p_q1l[(size_t)PM*PD];
__device__ bf16 p_v1h[(size_t)PM*PD], p_v1l[(size_t)PM*PD];

// ---------------- helpers ----------------
__device__ __forceinline__ uint32_t smem_u32(const void* p) {
    uint32_t a;
    asm("{ .reg .u64 t; cvta.to.shared.u64 t, %1; cvt.u32.u64 %0, t; }"
        : "=r"(a) : "l"(p));
    return a;
}
__device__ __forceinline__ float warpMax(float v) {
#pragma unroll
    for (int o = 16; o; o >>= 1) v = fmaxf(v, __shfl_xor_sync(0xffffffffu, v, o));
    return v;
}
__device__ __forceinline__ float warpSum(float v) {
#pragma unroll
    for (int o = 16; o; o >>= 1) v += __shfl_xor_sync(0xffffffffu, v, o);
    return v;
}
// bf16 split (attention path)
__device__ __forceinline__ uint32_t split_pack(float x, float y, uint32_t& lo_pack) {
    bf16 hx = __float2bfloat16_rn(x);
    bf16 hy = __float2bfloat16_rn(y);
    bf16 lx = __float2bfloat16_rn(x - __bfloat162float(hx));
    bf16 ly = __float2bfloat16_rn(y - __bfloat162float(hy));
    lo_pack = ((uint32_t)__bfloat16_as_ushort(ly) << 16) | (uint32_t)__bfloat16_as_ushort(lx);
    return ((uint32_t)__bfloat16_as_ushort(hy) << 16) | (uint32_t)__bfloat16_as_ushort(hx);
}
__device__ __forceinline__ uint32_t hpack(float x, float y) {
    return ((uint32_t)__half_as_ushort(__float2half_rn(y)) << 16) |
           (uint32_t)__half_as_ushort(__float2half_rn(x));
}
__device__ __forceinline__ void ldsm_x4(uint32_t* r, uint32_t addr) {
    asm volatile("ldmatrix.sync.aligned.m8n8.x4.shared.b16 {%0,%1,%2,%3}, [%4];"
                 : "=r"(r[0]), "=r"(r[1]), "=r"(r[2]), "=r"(r[3]) : "r"(addr));
}
__device__ __forceinline__ void ldsm_x2(uint32_t* r, uint32_t addr) {
    asm volatile("ldmatrix.sync.aligned.m8n8.x2.shared.b16 {%0,%1}, [%2];"
                 : "=r"(r[0]), "=r"(r[1]) : "r"(addr));
}
__device__ __forceinline__ void ldsm_x2t(uint32_t* r, uint32_t addr) {
    asm volatile("ldmatrix.sync.aligned.m8n8.x2.trans.shared.b16 {%0,%1}, [%2];"
                 : "=r"(r[0]), "=r"(r[1]) : "r"(addr));
}
__device__ __forceinline__ void mma_bf16(float c[4], const uint32_t a[4], const uint32_t b[2]) {
    asm volatile(
        "mma.sync.aligned.m16n8k16.row.col.f32.bf16.bf16.f32 "
        "{%0,%1,%2,%3}, {%4,%5,%6,%7}, {%8,%9}, {%0,%1,%2,%3};"
        : "+f"(c[0]), "+f"(c[1]), "+f"(c[2]), "+f"(c[3])
        : "r"(a[0]), "r"(a[1]), "r"(a[2]), "r"(a[3]), "r"(b[0]), "r"(b[1]));
}
__device__ __forceinline__ void mma_f16(float c[4], const uint32_t a[4], const uint32_t b[2]) {
    asm volatile(
        "mma.sync.aligned.m16n8k16.row.col.f32.f16.f16.f32 "
        "{%0,%1,%2,%3}, {%4,%5,%6,%7}, {%8,%9}, {%0,%1,%2,%3};"
        : "+f"(c[0]), "+f"(c[1]), "+f"(c[2]), "+f"(c[3])
        : "r"(a[0]), "r"(a[1]), "r"(a[2]), "r"(a[3]), "r"(b[0]), "r"(b[1]));
}
__device__ __forceinline__ void cp16(uint32_t dst, const void* src) {
    asm volatile("cp.async.cg.shared.global [%0], [%1], 16;"
                 :: "r"(dst), "l"(src) : "memory");
}
#define CP_COMMIT() asm volatile("cp.async.commit_group;" ::: "memory")
#define CP_WAIT1()  asm volatile("cp.async.wait_group 1;" ::: "memory")
#define CP_WAIT0()  asm volatile("cp.async.wait_group 0;" ::: "memory")

// ---------------- fp32 -> fp16 conversion (all tensors, one launch) ----------------
struct ConvDesc { const float* s; f16* h; int n4; };
struct ConvArgs { ConvDesc d[7]; };

__global__ __launch_bounds__(256) void conv_all(ConvArgs a)
{
    ConvDesc d = a.d[blockIdx.y];
    int i = blockIdx.x * 256 + threadIdx.x;
    if (i < d.n4) {
        float4 v = ((const float4*)d.s)[i];
        ((uint2*)d.h)[i] = make_uint2(hpack(v.x, v.y), hpack(v.z, v.w));
    }
}

// ======================= pure fp16 tensor-core GEMM (cp.async) =======================
// C[M,N] = A[M,K] @ W[K,N] + bias. A, W: fp16 single plane. 1 MMA per tile pair.
// Tile 128x128, K-chunk 32, 2-stage, 256 threads, 2 CTAs/SM.
// OUTMODE: 0 = fp32, 1 = bf16 pair (attention q/v), 2 = fp16 hi + ReLU (FFN hidden).
#define SA    0
#define SB    10240
#define STAGE 18944
#define GEMM_SMEM (2 * STAGE)

template <int OUTMODE>
__device__ __forceinline__ void gemm_core(
    const f16* __restrict__ A, const f16* __restrict__ W,
    const float* __restrict__ bias,
    float* __restrict__ C, bf16* __restrict__ Ch, bf16* __restrict__ Cl,
    f16* __restrict__ Hh,
    int Mv, int Nv, int Kv, char* smem_raw)
{
    const uint32_t smb = smem_u32(smem_raw);
    const int tid = threadIdx.x;
    const int lane = tid & 31;
    const int wid = tid >> 5;
    const int wm = (wid >> 2) * 64;
    const int wn = (wid & 3) * 32;
    const int by = blockIdx.y * 128;
    const int bx = blockIdx.x * 128;
    const int nC = Kv >> 5;

    float c[4][4][4] = {};
    const int aRow = (lane & 7) + ((lane >> 3) & 1) * 8;
    const int aCol = (lane >> 4) * 8;
    const int bRow = lane & 15;

    auto issue = [&](int ck) {
        const uint32_t sb = smb + (ck & 1) * STAGE;
        const int k0 = ck * 32;
#pragma unroll
        for (int i = 0; i < 2; i++) {               // A: 128 rows x 64B
            int idx = tid + i * 256;
            int r = idx >> 2, s = idx & 3;
            cp16(sb + SA + r * 80 + s * 16, A + (size_t)(by + r) * Kv + k0 + s * 8);
        }
#pragma unroll
        for (int i = 0; i < 2; i++) {               // B: 32 rows x 256B
            int idx = tid + i * 256;
            int r = idx >> 4, s = idx & 15;
            cp16(sb + SB + r * 272 + s * 16, W + (size_t)(k0 + r) * Nv + bx + s * 8);
        }
        CP_COMMIT();
    };

    issue(0);

    for (int ck = 0; ck < nC; ck++) {
        if (ck + 1 < nC) { issue(ck + 1); CP_WAIT1(); }
        else             { CP_WAIT0(); }
        __syncthreads();

        const uint32_t sb = smb + (ck & 1) * STAGE;
#pragma unroll
        for (int ks = 0; ks < 32; ks += 16) {
            uint32_t ah[4][4], bh[4][2];
#pragma unroll
            for (int mt = 0; mt < 4; mt++) {
                uint32_t off = (uint32_t)((wm + mt * 16 + aRow) * 80 + (ks + aCol) * 2);
                ldsm_x4(ah[mt], sb + SA + off);
            }
#pragma unroll
            for (int nt = 0; nt < 4; nt++) {
                uint32_t off = (uint32_t)((ks + bRow) * 272 + (wn + nt * 8) * 2);
                ldsm_x2t(bh[nt], sb + SB + off);
            }
#pragma unroll
            for (int mt = 0; mt < 4; mt++)
#pragma unroll
                for (int nt = 0; nt < 4; nt++)
                    mma_f16(c[mt][nt], ah[mt], bh[nt]);
        }
        __syncthreads();
    }

    const int g = lane >> 2, t = lane & 3;
#pragma unroll
    for (int mt = 0; mt < 4; mt++) {
#pragma unroll
        for (int nt = 0; nt < 4; nt++) {
            int row = by + wm + mt * 16 + g;
            int col = bx + wn + nt * 8 + 2 * t;
            float2 bv = *(const float2*)(bias + col);
            float v00 = c[mt][nt][0] + bv.x, v01 = c[mt][nt][1] + bv.y;
            float v10 = c[mt][nt][2] + bv.x, v11 = c[mt][nt][3] + bv.y;
            if (OUTMODE == 2) {
                v00 = fmaxf(v00, 0.f); v01 = fmaxf(v01, 0.f);
                v10 = fmaxf(v10, 0.f); v11 = fmaxf(v11, 0.f);
            }
            if (OUTMODE == 0) {
                *(float2*)(C + (size_t)row * Nv + col) = make_float2(v00, v01);
                *(float2*)(C + (size_t)(row + 8) * Nv + col) = make_float2(v10, v11);
            } else if (OUTMODE == 1) {
                uint32_t lo0, lo1;
                uint32_t h0 = split_pack(v00, v01, lo0);
                uint32_t h1 = split_pack(v10, v11, lo1);
                *(uint32_t*)(Ch + (size_t)row * Nv + col) = h0;
                *(uint32_t*)(Cl + (size_t)row * Nv + col) = lo0;
                *(uint32_t*)(Ch + (size_t)(row + 8) * Nv + col) = h1;
                *(uint32_t*)(Cl + (size_t)(row + 8) * Nv + col) = lo1;
            } else {
                *(uint32_t*)(Hh + (size_t)row * Nv + col) = hpack(v00, v01);
                *(uint32_t*)(Hh + (size_t)(row + 8) * Nv + col) = hpack(v10, v11);
            }
        }
    }
}

template <int OUTMODE>
__global__ __launch_bounds__(256, 2)
void gemm_mma(const f16* __restrict__ A, const f16* __restrict__ W,
              const float* __restrict__ bias,
              float* __restrict__ C, bf16* __restrict__ Ch, bf16* __restrict__ Cl,
              f16* __restrict__ Hh, int Mv, int Nv, int Kv)
{
    extern __shared__ __align__(128) char smem_raw[];
    gemm_core<OUTMODE>(A, W, bias, C, Ch, Cl, Hh, Mv, Nv, Kv, smem_raw);
}

// multi-set GEMM: blockIdx.z selects pointer set
struct GSet  { const f16 *A, *W; const float* bias; float* C; bf16 *Ch, *Cl; f16* Hh; };
struct GSets { GSet s[4]; };

template <int OUTMODE>
__global__ __launch_bounds__(256, 2)
void gemm_multi(GSets sets, int Mv, int Nv, int Kv)
{
    extern __shared__ __align__(128) char smem_raw[];
    GSet g = sets.s[blockIdx.z];
    gemm_core<OUTMODE>(g.A, g.W, g.bias, g.C, g.Ch, g.Cl, g.Hh,
                       Mv, Nv, Kv, smem_raw);
}

// ---------------- fused add + LayerNorm (warp-per-row) ----------------
// MODE: 0 = fp32 only, 1 = fp16 hi only, 2 = fp32 + fp16 hi
template <int MODE>
__device__ __forceinline__ void add_ln_row(
    int row,
    const float* __restrict__ A, const float* __restrict__ Bv,
    const float* __restrict__ g, const float* __restrict__ be,
    float* __restrict__ outF, f16* __restrict__ outH)
{
    const int lane = threadIdx.x & 31;
    float4 x4[4];
    float sum = 0.f;
#pragma unroll
    for (int i = 0; i < 4; i++) {
        int idx = lane + i * 32;
        float4 xa = ((const float4*)(A  + (size_t)row * PD))[idx];
        float4 xb = ((const float4*)(Bv + (size_t)row * PD))[idx];
        x4[i].x = xa.x + xb.x; x4[i].y = xa.y + xb.y;
        x4[i].z = xa.z + xb.z; x4[i].w = xa.w + xb.w;
        sum += x4[i].x + x4[i].y + x4[i].z + x4[i].w;
    }
    float mean = warpSum(sum) * (1.0f / PD);
    float vs = 0.f;
#pragma unroll
    for (int i = 0; i < 4; i++) {
        x4[i].x -= mean; x4[i].y -= mean; x4[i].z -= mean; x4[i].w -= mean;
        vs += x4[i].x * x4[i].x + x4[i].y * x4[i].y +
              x4[i].z * x4[i].z + x4[i].w * x4[i].w;
    }
    float rstd = rsqrtf(warpSum(vs) * (1.0f / PD) + LN_EPS);
#pragma unroll
    for (int i = 0; i < 4; i++) {
        int idx = lane + i * 32;
        float4 gg = ((const float4*)g)[idx];
        float4 bb = ((const float4*)be)[idx];
        float o0 = x4[i].x * rstd * gg.x + bb.x;
        float o1 = x4[i].y * rstd * gg.y + bb.y;
        float o2 = x4[i].z * rstd * gg.z + bb.z;
        float o3 = x4[i].w * rstd * gg.w + bb.w;
        if (MODE != 1)
            ((float4*)(outF + (size_t)row * PD))[idx] = make_float4(o0, o1, o2, o3);
        if (MODE != 0)
            ((uint2*)(outH + (size_t)row * PD))[idx] =
                make_uint2(hpack(o0, o1), hpack(o2, o3));
    }
}

template <int MODE>
__global__ __launch_bounds__(256) void add_ln_kernel(
    const float* __restrict__ A, const float* __restrict__ Bv,
    const float* __restrict__ g, const float* __restrict__ be,
    float* __restrict__ outF, f16* __restrict__ outH)
{
    int row = blockIdx.x * 8 + (threadIdx.x >> 5);
    add_ln_row<MODE>(row, A, Bv, g, be, outF, outH);
}

__global__ __launch_bounds__(256) void add_ln_dual(
    const float* A0, const float* B0, const float* g0, const float* be0,
    float* f0, f16* h0,
    const float* A1, const float* B1, const float* g1, const float* be1,
    float* f1, f16* h1)
{
    int row = blockIdx.x * 8 + (threadIdx.x >> 5);
    if (blockIdx.y == 0)
        add_ln_row<2>(row, A0, B0, g0, be0, f0, h0);
    else
        add_ln_row<2>(row, A1, B1, g1, be1, f1, h1);
}

// ---------------- fused distance-decay attention (bf16x3, unchanged) ----------------
#define AQ_H 0
#define AQ_L 4608
#define AK_H 9216
#define AK_L 27648
#define A_SS 46080
#define ATT_SMEM 112640

__device__ __forceinline__ void attn_core(
    const bf16* __restrict__ Qh, const bf16* __restrict__ Ql,
    const bf16* __restrict__ Vh, const bf16* __restrict__ Vl,
    const float* __restrict__ gammas, int layer, int strict,
    f16* __restrict__ O, char* sm_raw)
{
    const uint32_t smb = smem_u32(sm_raw);
    float* sS = (float*)(sm_raw + A_SS);

    const int bh = blockIdx.y;
    const int b = bh >> 3, h = bh & 7;
    const int i0 = blockIdx.x * 32;
    const int tid = threadIdx.x;
    const int lane = tid & 31, w = tid >> 5;

    int nCh = (i0 + 32 + 127) >> 7;
    if (strict && i0 == 0) nCh = 4;
    const int jEnd = nCh * 128;

    float gamma = gammas[layer * PH + h];
    float gneg = (gamma > 20.f) ? -gamma : -log1pf(expf(gamma));

    const size_t headOff = (size_t)(b * PS) * PD + h * PDK;
    const bf16* Qbh = Qh + headOff;
    const bf16* Qbl = Ql + headOff;
    const bf16* Vbh = Vh + headOff;
    const bf16* Vbl = Vl + headOff;

    const int aRow = (lane & 7) + ((lane >> 3) & 1) * 8;
    const int aCol = (lane >> 4) * 8;
    const int g = lane >> 2, t = lane & 3;

    {
        int r = tid >> 3, s = tid & 7;
        *(uint4*)(sm_raw + AQ_H + r * 144 + s * 16) =
            *(const uint4*)(Qbh + (size_t)(i0 + r) * PD + s * 8);
        *(uint4*)(sm_raw + AQ_L + r * 144 + s * 16) =
            *(const uint4*)(Qbl + (size_t)(i0 + r) * PD + s * 8);
    }

    for (int j0 = 0; j0 < jEnd; j0 += 128) {
#pragma unroll
        for (int i = 0; i < 4; i++) {
            int idx = tid + i * 256;
            int r = idx >> 3, s = idx & 7;
            *(uint4*)(sm_raw + AK_H + r * 144 + s * 16) =
                *(const uint4*)(Qbh + (size_t)(j0 + r) * PD + s * 8);
            *(uint4*)(sm_raw + AK_L + r * 144 + s * 16) =
                *(const uint4*)(Qbl + (size_t)(j0 + r) * PD + s * 8);
        }
        __syncthreads();

        float acc[2][2][4] = {};
#pragma unroll
        for (int ks = 0; ks < 64; ks += 16) {
            uint32_t ah[2][4], al[2][4], kh[2][2], kl[2][2];
#pragma unroll
            for (int mt = 0; mt < 2; mt++) {
                uint32_t off = (uint32_t)((mt * 16 + aRow) * 144 + (ks + aCol) * 2);
                ldsm_x4(ah[mt], smb + AQ_H + off);
                ldsm_x4(al[mt], smb + AQ_L + off);
            }
#pragma unroll
            for (int nf = 0; nf < 2; nf++) {
                uint32_t off = (uint32_t)((w * 16 + nf * 8 + (lane & 7)) * 144 +
                                          (ks + ((lane >> 3) & 1) * 8) * 2);
                ldsm_x2(kh[nf], smb + AK_H + off);
                ldsm_x2(kl[nf], smb + AK_L + off);
            }
#pragma unroll
            for (int mt = 0; mt < 2; mt++)
#pragma unroll
                for (int nf = 0; nf < 2; nf++) {
                    mma_bf16(acc[mt][nf], ah[mt], kh[nf]);
                    mma_bf16(acc[mt][nf], ah[mt], kl[nf]);
                    mma_bf16(acc[mt][nf], al[mt], kh[nf]);
                }
        }
        const float scale = 0.125f;
#pragma unroll
        for (int mt = 0; mt < 2; mt++)
#pragma unroll
            for (int nf = 0; nf < 2; nf++) {
                int r0 = mt * 16 + g;
                int col = j0 + w * 16 + nf * 8 + 2 * t;
                *(float2*)&sS[r0 * 520 + col] =
                    make_float2(acc[mt][nf][0] * scale, acc[mt][nf][1] * scale);
                *(float2*)&sS[(r0 + 8) * 520 + col] =
                    make_float2(acc[mt][nf][2] * scale, acc[mt][nf][3] * scale);
            }
        __syncthreads();
    }

    const float NEG = -1e32f;
    for (int rr = 0; rr < 4; rr++) {
        const int il = w + rr * 8;
        const int ig = i0 + il;
        const uint32_t pSw = (uint32_t)(((il >> 2) & 1) * 16);
        float sraw[16], p[16], cum[16];
        float mx = NEG;
#pragma unroll
        for (int c = 0; c < 16; c++) {
            int j = lane + 32 * c;
            sraw[c] = sS[il * 520 + j];
            bool vld = strict ? (j < ig) : (j <= ig);
            float s1 = vld ? sraw[c] : NEG;
            p[c] = s1;
            mx = fmaxf(mx, s1);
        }
        mx = warpMax(mx);
        float sum = 0.f;
#pragma unroll
        for (int c = 0; c < 16; c++) { float e = __expf(p[c] - mx); p[c] = e; sum += e; }
        sum = warpSum(sum);
        float inv = 1.0f / sum;
#pragma unroll
        for (int c = 0; c < 16; c++) {
            int j = lane + 32 * c;
            bool vld = strict ? (j < ig) : (j <= ig);
            p[c] = vld ? p[c] * inv : 0.f;
        }
        float run = 0.f;
#pragma unroll
        for (int c = 0; c < 16; c++) {
            float sc = p[c];
#pragma unroll
            for (int o = 1; o < 32; o <<= 1) {
                float tt = __shfl_up_sync(0xffffffffu, sc, o);
                if (lane >= o) sc += tt;
            }
            cum[c] = run + sc;
            run += __shfl_sync(0xffffffffu, sc, 31);
        }
        const float tot = run;
        float m2 = NEG;
#pragma unroll
        for (int c = 0; c < 16; c++) {
            int j = lane + 32 * c;
            bool vld = strict ? (j < ig) : (j <= ig);
            float pos = fabsf((float)(ig - j));
            float dist = sqrtf(fmaxf((tot - cum[c]) * pos, 0.f));
            float eff = __expf(gneg * dist);
            eff = fminf(fmaxf(eff, 1e-5f), 1e5f);
            float v2 = vld ? sraw[c] * eff : NEG;
            p[c] = v2;
            m2 = fmaxf(m2, v2);
        }
        m2 = warpMax(m2);
        float sum2 = 0.f;
#pragma unroll
        for (int c = 0; c < 16; c++) { float e = __expf(p[c] - m2); p[c] = e; sum2 += e; }
        sum2 = warpSum(sum2);
        float inv2 = 1.0f / sum2;
#pragma unroll
        for (int c = 0; c < 16; c++) {
            int j = lane + 32 * c;
            float val = p[c] * inv2;
            bf16 hi = __float2bfloat16_rn(val);
            bf16 lo = __float2bfloat16_rn(val - __bfloat162float(hi));
            *(unsigned short*)(sm_raw + A_SS + il * 2080 + pSw + 2 * j) =
                __bfloat16_as_ushort(hi);
            *(unsigned short*)(sm_raw + A_SS + il * 2080 + 1040 + pSw + 2 * j) =
                __bfloat16_as_ushort(lo);
        }
    }
    __syncthreads();

    float acco[2][4] = {};
    for (int j0 = 0; j0 < jEnd; j0 += 128) {
#pragma unroll
        for (int i = 0; i < 4; i++) {
            int idx = tid + i * 256;
            int r = idx >> 3, s = idx & 7;
            *(uint4*)(sm_raw + AK_H + r * 144 + s * 16) =
                *(const uint4*)(Vbh + (size_t)(j0 + r) * PD + s * 8);
            *(uint4*)(sm_raw + AK_L + r * 144 + s * 16) =
                *(const uint4*)(Vbl + (size_t)(j0 + r) * PD + s * 8);
        }
        __syncthreads();
#pragma unroll
        for (int ks = 0; ks < 8; ks++) {
            uint32_t ph[2][4], pl[2][4], vh[2], vl[2];
#pragma unroll
            for (int mt = 0; mt < 2; mt++) {
                int prow = mt * 16 + aRow;
                uint32_t off = (uint32_t)(prow * 2080 + ((prow >> 2) & 1) * 16 +
                                          (j0 + ks * 16 + aCol) * 2);
                ldsm_x4(ph[mt], smb + A_SS + off);
                ldsm_x4(pl[mt], smb + A_SS + 1040 + off);
            }
            {
                uint32_t off = (uint32_t)((ks * 16 + (lane & 15)) * 144 + (w * 8) * 2);
                ldsm_x2t(vh, smb + AK_H + off);
                ldsm_x2t(vl, smb + AK_L + off);
            }
#pragma unroll
            for (int mt = 0; mt < 2; mt++) {
                mma_bf16(acco[mt], ph[mt], vh);
                mma_bf16(acco[mt], ph[mt], vl);
                mma_bf16(acco[mt], pl[mt], vh);
            }
        }
        __syncthreads();
    }

    // ---- write O as fp16 hi plane (A side of Wo GEMM) ----
#pragma unroll
    for (int mt = 0; mt < 2; mt++) {
        int r0 = b * PS + i0 + mt * 16 + g;
        int col = h * PDK + w * 8 + 2 * t;
        *(uint32_t*)(O + (size_t)r0 * PD + col) = hpack(acco[mt][0], acco[mt][1]);
        *(uint32_t*)(O + (size_t)(r0 + 8) * PD + col) = hpack(acco[mt][2], acco[mt][3]);
    }
}

__global__ __launch_bounds__(256, 2) void attn_mma(
    const bf16* Qh, const bf16* Ql, const bf16* Vh, const bf16* Vl,
    const float* gammas, int layer, int strict, f16* O)
{
    extern __shared__ __align__(128) char sm_raw[];
    attn_core(Qh, Ql, Vh, Vl, gammas, layer, strict, O, sm_raw);
}

__global__ __launch_bounds__(256, 2) void attn_dual(
    const bf16* Q0h, const bf16* Q0l, const bf16* V0h, const bf16* V0l, f16* O0,
    const bf16* Q1h, const bf16* Q1l, const bf16* V1h, const bf16* V1l, f16* O1,
    const float* gammas)
{
    extern __shared__ __align__(128) char sm_raw[];
    const int z = blockIdx.z;
    attn_core(z ? Q1h : Q0h, z ? Q1l : Q0l, z ? V1h : V0h, z ? V1l : V0l,
              gammas, z, 0, z ? O1 : O0, sm_raw);
}

// ---------------- host orchestration ----------------
static void run_gemm(int mode, const f16* A, const f16* W,
                     const float* bias, float* C, bf16* Ch, bf16* Cl, f16* Hh,
                     int Mv, int Nv, int Kv)
{
    dim3 grid(Nv / 128, Mv / 128);
    if (mode == 0)      gemm_mma<0><<<grid, 256, GEMM_SMEM>>>(A, W, bias, C, Ch, Cl, Hh, Mv, Nv, Kv);
    else if (mode == 1) gemm_mma<1><<<grid, 256, GEMM_SMEM>>>(A, W, bias, C, Ch, Cl, Hh, Mv, Nv, Kv);
    else                gemm_mma<2><<<grid, 256, GEMM_SMEM>>>(A, W, bias, C, Ch, Cl, Hh, Mv, Nv, Kv);
}

extern "C" void kernel_launch(void* const* d_in, const int* in_sizes, int n_in,
                              void* d_out, int out_size)
{
    const float* q_embed  = (const float*)d_in[0];
    const float* qa_embed = (const float*)d_in[1];
    const float* Wk  = (const float*)d_in[2];
    const float* bk  = (const float*)d_in[3];
    const float* Wv  = (const float*)d_in[4];
    const float* bv  = (const float*)d_in[5];
    const float* Wo  = (const float*)d_in[6];
    const float* bo  = (const float*)d_in[7];
    const float* gam = (const float*)d_in[8];
    const float* l1g = (const float*)d_in[9];
    const float* l1b = (const float*)d_in[10];
    const float* W1  = (const float*)d_in[11];
    const float* b1  = (const float*)d_in[12];
    const float* W2  = (const float*)d_in[13];
    const float* b2  = (const float*)d_in[14];
    const float* l2g = (const float*)d_in[15];
    const float* l2b = (const float*)d_in[16];
    float* out = (float*)d_out;

    float *ga, *ga1, *gt, *gx;
    cudaGetSymbolAddress((void**)&ga,  g_a);
    cudaGetSymbolAddress((void**)&ga1, g_a1);
    cudaGetSymbolAddress((void**)&gt,  g_t);
    cudaGetSymbolAddress((void**)&gx,  g_x);
#define SYMH(p, s) f16* p; cudaGetSymbolAddress((void**)&p, s)
#define SYMB(p, s) bf16* p; cudaGetSymbolAddress((void**)&p, s)
    SYMH(e1, p_e1); SYMH(e2, p_e2);
    SYMH(po, p_o);  SYMH(po1, p_o1);
    SYMH(pt, p_t);  SYMH(py, p_y);  SYMH(px, p_x);  SYMH(ph, p_hbuf);
    SYMH(wk, p_wk); SYMH(wv, p_wv); SYMH(wo, p_wo);
    SYMH(w1, p_w1); SYMH(w2, p_w2);
    SYMB(qh, p_qh);   SYMB(ql, p_ql);   SYMB(vh, p_vh);   SYMB(vl, p_vl);
    SYMB(q1h, p_q1h); SYMB(q1l, p_q1l); SYMB(v1h, p_v1h); SYMB(v1l, p_v1l);
#undef SYMH
#undef SYMB

    cudaFuncSetAttribute(attn_mma,  cudaFuncAttributeMaxDynamicSharedMemorySize, ATT_SMEM);
    cudaFuncSetAttribute(attn_dual, cudaFuncAttributeMaxDynamicSharedMemorySize, ATT_SMEM);
    cudaFuncSetAttribute(gemm_mma<0>, cudaFuncAttributeMaxDynamicSharedMemorySize, GEMM_SMEM);
    cudaFuncSetAttribute(gemm_mma<1>, cudaFuncAttributeMaxDynamicSharedMemorySize, GEMM_SMEM);
    cudaFuncSetAttribute(gemm_mma<2>, cudaFuncAttributeMaxDynamicSharedMemorySize, GEMM_SMEM);
    cudaFuncSetAttribute(gemm_multi<0>, cudaFuncAttributeMaxDynamicSharedMemorySize, GEMM_SMEM);
    cudaFuncSetAttribute(gemm_multi<1>, cudaFuncAttributeMaxDynamicSharedMemorySize, GEMM_SMEM);

    const size_t DD = (size_t)PD * PD, DF = (size_t)PD * PF;

    // ---- preconvert: embeds + weights, fp16 single plane ----
    {
        ConvArgs ca;
        ca.d[0] = { q_embed,  e1, (int)((size_t)PM * PD / 4) };
        ca.d[1] = { qa_embed, e2, (int)((size_t)PM * PD / 4) };
        ca.d[2] = { Wk, wk, (int)(3 * DD / 4) };
        ca.d[3] = { Wv, wv, (int)(3 * DD / 4) };
        ca.d[4] = { Wo, wo, (int)(3 * DD / 4) };
        ca.d[5] = { W1, w1, (int)(3 * DF / 4) };
        ca.d[6] = { W2, w2, (int)(3 * DF / 4) };
        int maxn4 = (int)((size_t)PM * PD / 4);
        conv_all<<<dim3((maxn4 + 255) / 256, 7), 256>>>(ca);
    }

    // ===== Phase 1: blocks 0 & 1 fused (independent chains) =====
    {
        GSets s;
        s.s[0] = { e2, wk + 0 * DD, bk + 0 * PD, nullptr, qh,  ql,  nullptr };
        s.s[1] = { e2, wv + 0 * DD, bv + 0 * PD, nullptr, vh,  vl,  nullptr };
        s.s[2] = { e1, wk + 1 * DD, bk + 1 * PD, nullptr, q1h, q1l, nullptr };
        s.s[3] = { e1, wv + 1 * DD, bv + 1 * PD, nullptr, v1h, v1l, nullptr };
        gemm_multi<1><<<dim3(PD / 128, PM / 128, 4), 256, GEMM_SMEM>>>(s, PM, PD, PD);
    }
    attn_dual<<<dim3(PS / 32, PB * PH, 2), 256, ATT_SMEM>>>(
        qh, ql, vh, vl, po, q1h, q1l, v1h, v1l, po1, gam);
    {
        GSets s;
        s.s[0] = { po,  wo + 0 * DD, bo + 0 * PD, ga,  nullptr, nullptr, nullptr };
        s.s[1] = { po1, wo + 1 * DD, bo + 1 * PD, ga1, nullptr, nullptr, nullptr };
        s.s[2] = s.s[0]; s.s[3] = s.s[0];
        gemm_multi<0><<<dim3(PD / 128, PM / 128, 2), 256, GEMM_SMEM>>>(s, PM, PD, PD);
    }
    add_ln_dual<<<dim3(PM / 8, 2), 256>>>(
        qa_embed, ga,  l1g + 0 * PD, l1b + 0 * PD, gt, pt,
        q_embed,  ga1, l1g + 1 * PD, l1b + 1 * PD, gx, px);

    // block 0 FFN
    run_gemm(2, pt, w1 + 0 * DF, b1 + 0 * PF, nullptr, nullptr, nullptr, ph, PM, PF, PD);
    run_gemm(0, ph, w2 + 0 * DF, b2 + 0 * PD, ga, nullptr, nullptr, nullptr, PM, PD, PF);
    add_ln_kernel<1><<<PM / 8, 256>>>(gt, ga, l2g + 0 * PD, l2b + 0 * PD, nullptr, py);

    // ===== Block 2: knowledge retriever (q/k from x, v from y, strict mask, FFN) =====
    {
        GSets s;
        s.s[0] = { px, wk + 2 * DD, bk + 2 * PD, nullptr, qh, ql, nullptr };
        s.s[1] = { py, wv + 2 * DD, bv + 2 * PD, nullptr, vh, vl, nullptr };
        s.s[2] = s.s[0]; s.s[3] = s.s[0];
        gemm_multi<1><<<dim3(PD / 128, PM / 128, 2), 256, GEMM_SMEM>>>(s, PM, PD, PD);
    }
    attn_mma<<<dim3(PS / 32, PB * PH), 256, ATT_SMEM>>>(qh, ql, vh, vl, gam, 2, 1, po);
    run_gemm(0, po, wo + 2 * DD, bo + 2 * PD, ga, nullptr, nullptr, nullptr, PM, PD, PD);
    add_ln_kernel<2><<<PM / 8, 256>>>(gx, ga, l1g + 2 * PD, l1b + 2 * PD, gt, pt);
    run_gemm(2, pt, w1 + 2 * DF, b1 + 2 * PF, nullptr, nullptr, nullptr, ph, PM, PF, PD);
    run_gemm(0, ph, w2 + 2 * DF, b2 + 2 * PD, ga, nullptr, nullptr, nullptr, PM, PD, PF);
    add_ln_kernel<0><<<PM / 8, 256>>>(gt, ga, l2g + 2 * PD, l2b + 2 * PD, out, nullptr);
}